// round 1
// baseline (speedup 1.0000x reference)
#include <cuda_runtime.h>
#include <cuda_bf16.h>
#include <math_constants.h>

// Problem constants
#define BATCH   2
#define SEQ     2048
#define CMODEL  1024
#define NHEADS  16
#define DHEAD   64
#define MROWS   (BATCH * SEQ)          // 4096
#define QKV_N   (3 * CMODEL)           // 3072

// Scratch (allocation-free rule: __device__ globals)
__device__ float g_qkv[(size_t)MROWS * QKV_N];   // [4096, 3072]  Q|K|V concat
__device__ float g_y[(size_t)MROWS * CMODEL];    // [4096, 1024]  attention out

// ---------------------------------------------------------------------------
// SGEMM with fused bias: C[M,N] = A[M,K] @ B[K,N] + bias[N]
// 128x128 block tile, BK=16, 256 threads, 8x8 per-thread micro-tile.
// ---------------------------------------------------------------------------
#define BM 128
#define BN 128
#define BKK 16

__global__ __launch_bounds__(256, 2)
void sgemm_bias_kernel(const float* __restrict__ A,
                       const float* __restrict__ B,
                       const float* __restrict__ bias,
                       float* __restrict__ C,
                       int M, int N, int K)
{
    __shared__ float As[BKK][BM];   // transposed A tile
    __shared__ float Bs[BKK][BN];

    const int tid  = threadIdx.x;
    const int tcol = tid & 15;      // 0..15
    const int trow = tid >> 4;      // 0..15
    const int rowBase = blockIdx.y * BM;
    const int colBase = blockIdx.x * BN;

    float acc[8][8];
#pragma unroll
    for (int i = 0; i < 8; i++)
#pragma unroll
        for (int j = 0; j < 8; j++) acc[i][j] = 0.f;

    for (int k0 = 0; k0 < K; k0 += BKK) {
        // Load A tile: 128 rows x 16 cols = 512 float4
#pragma unroll
        for (int i = 0; i < 2; i++) {
            int idx = tid + i * 256;
            int r  = idx >> 2;          // 4 float4 per row
            int c4 = idx & 3;
            float4 a = *(const float4*)&A[(size_t)(rowBase + r) * K + k0 + c4 * 4];
            As[c4 * 4 + 0][r] = a.x;
            As[c4 * 4 + 1][r] = a.y;
            As[c4 * 4 + 2][r] = a.z;
            As[c4 * 4 + 3][r] = a.w;
        }
        // Load B tile: 16 rows x 128 cols = 512 float4
#pragma unroll
        for (int i = 0; i < 2; i++) {
            int idx = tid + i * 256;
            int r  = idx >> 5;          // 32 float4 per row
            int c4 = idx & 31;
            *(float4*)&Bs[r][c4 * 4] =
                *(const float4*)&B[(size_t)(k0 + r) * N + colBase + c4 * 4];
        }
        __syncthreads();

#pragma unroll
        for (int k = 0; k < BKK; k++) {
            float ra[8], rb[8];
#pragma unroll
            for (int i = 0; i < 8; i++) ra[i] = As[k][trow * 8 + i];
#pragma unroll
            for (int j = 0; j < 8; j++) rb[j] = Bs[k][tcol * 8 + j];
#pragma unroll
            for (int i = 0; i < 8; i++)
#pragma unroll
                for (int j = 0; j < 8; j++)
                    acc[i][j] += ra[i] * rb[j];
        }
        __syncthreads();
    }

    // Epilogue: add bias, vectorized store
#pragma unroll
    for (int i = 0; i < 8; i++) {
        int r = rowBase + trow * 8 + i;
#pragma unroll
        for (int j4 = 0; j4 < 2; j4++) {
            int c = colBase + tcol * 8 + j4 * 4;
            float4 o;
            o.x = acc[i][j4 * 4 + 0] + bias[c + 0];
            o.y = acc[i][j4 * 4 + 1] + bias[c + 1];
            o.z = acc[i][j4 * 4 + 2] + bias[c + 2];
            o.w = acc[i][j4 * 4 + 3] + bias[c + 3];
            *(float4*)&C[(size_t)r * N + c] = o;
        }
    }
}

// ---------------------------------------------------------------------------
// Fused causal flash attention, fp32.
// Grid: (SEQ/64, BATCH*NHEADS). Block: 256 threads.
// Per block: 64 queries of one (b,h). Key tiles of 32.
// smem padding: Ks stride 65, Ss stride 33 (bank-conflict free access).
// ---------------------------------------------------------------------------
#define BQ 64
#define BKT 32
#define KS_LD 65
#define SS_LD 33

__global__ __launch_bounds__(256, 2)
void attn_kernel(const float* __restrict__ qkv, float* __restrict__ y)
{
    __shared__ float Qs[BQ * DHEAD];        // [64][64]
    __shared__ float Ks[BKT * KS_LD];       // [32][65]
    __shared__ float Vs[BKT * DHEAD];       // [32][64]
    __shared__ float Ss[BQ * SS_LD];        // [64][33]
    __shared__ float row_alpha[BQ];
    __shared__ float row_linv[BQ];

    const int tid = threadIdx.x;
    const int q0  = blockIdx.x * BQ;
    const int bh  = blockIdx.y;
    const int b   = bh >> 4;
    const int h   = bh & 15;

    const float* base = qkv + (size_t)b * SEQ * QKV_N + h * DHEAD;

    // Load Q tile: 64 rows x 64 cols = 1024 float4
#pragma unroll
    for (int i = 0; i < 4; i++) {
        int idx = tid + i * 256;
        int r  = idx >> 4;
        int c4 = idx & 15;
        float4 v = *(const float4*)&base[(size_t)(q0 + r) * QKV_N + c4 * 4];
        *(float4*)&Qs[r * DHEAD + c4 * 4] = v;
    }

    const int ty = tid >> 4;   // 0..15 -> 4 query rows each
    const int tx = tid & 15;   // 0..15

    float acc[4][4];
#pragma unroll
    for (int i = 0; i < 4; i++)
#pragma unroll
        for (int j = 0; j < 4; j++) acc[i][j] = 0.f;

    // per-row softmax state lives in registers of threads 0..63
    float m_run = -CUDART_INF_F;
    float l_run = 0.f;

    const int nkt = (q0 >> 5) + 2;   // key tiles with k0 <= q0+63

    for (int kt = 0; kt < nkt; kt++) {
        const int k0 = kt * BKT;
        __syncthreads();   // protect Ks/Vs/Ss from previous iteration readers

        // Load K (scalar stores, padded) and V tiles: 32 rows x 64 cols each
#pragma unroll
        for (int i = 0; i < 2; i++) {
            int idx = tid + i * 256;
            int r  = idx >> 4;
            int c4 = idx & 15;
            float4 kv = *(const float4*)&base[CMODEL + (size_t)(k0 + r) * QKV_N + c4 * 4];
            Ks[r * KS_LD + c4 * 4 + 0] = kv.x;
            Ks[r * KS_LD + c4 * 4 + 1] = kv.y;
            Ks[r * KS_LD + c4 * 4 + 2] = kv.z;
            Ks[r * KS_LD + c4 * 4 + 3] = kv.w;
            float4 vv = *(const float4*)&base[2 * CMODEL + (size_t)(k0 + r) * QKV_N + c4 * 4];
            *(float4*)&Vs[r * DHEAD + c4 * 4] = vv;
        }
        __syncthreads();

        // Phase 1: S = Q K^T (per thread: 4 rows x 2 key-cols)
        float s[4][2];
#pragma unroll
        for (int i = 0; i < 4; i++) { s[i][0] = 0.f; s[i][1] = 0.f; }
#pragma unroll 8
        for (int k = 0; k < DHEAD; k++) {
            float qa[4], kb[2];
#pragma unroll
            for (int i = 0; i < 4; i++) qa[i] = Qs[(ty * 4 + i) * DHEAD + k];
            kb[0] = Ks[(tx * 2 + 0) * KS_LD + k];
            kb[1] = Ks[(tx * 2 + 1) * KS_LD + k];
#pragma unroll
            for (int i = 0; i < 4; i++) {
                s[i][0] += qa[i] * kb[0];
                s[i][1] += qa[i] * kb[1];
            }
        }
#pragma unroll
        for (int i = 0; i < 4; i++) {
            int r = ty * 4 + i;
#pragma unroll
            for (int j = 0; j < 2; j++) {
                int c = tx * 2 + j;
                bool valid = (k0 + c) <= (q0 + r);
                Ss[r * SS_LD + c] = valid ? s[i][j] * 0.125f : -CUDART_INF_F;
            }
        }
        __syncthreads();

        // Phase 2: online softmax row update (threads 0..63, one row each)
        if (tid < BQ) {
            const int r = tid;
            float tm = -CUDART_INF_F;
#pragma unroll 8
            for (int j = 0; j < BKT; j++) tm = fmaxf(tm, Ss[r * SS_LD + j]);
            float mn = fmaxf(m_run, tm);
            float al = __expf(m_run - mn);   // first tile: exp(-inf)=0
            float sum = 0.f;
#pragma unroll 8
            for (int j = 0; j < BKT; j++) {
                float p = __expf(Ss[r * SS_LD + j] - mn);
                Ss[r * SS_LD + j] = p;
                sum += p;
            }
            l_run = al * l_run + sum;
            m_run = mn;
            row_alpha[r] = al;
        }
        __syncthreads();

        // Phase 3: O = alpha*O + P V (per thread: 4 rows x 4 d-cols)
        float alr[4];
#pragma unroll
        for (int i = 0; i < 4; i++) {
            alr[i] = row_alpha[ty * 4 + i];
#pragma unroll
            for (int j = 0; j < 4; j++) acc[i][j] *= alr[i];
        }
#pragma unroll 4
        for (int kk = 0; kk < BKT; kk++) {
            float4 v4 = *(const float4*)&Vs[kk * DHEAD + tx * 4];
            float p[4];
#pragma unroll
            for (int i = 0; i < 4; i++) p[i] = Ss[(ty * 4 + i) * SS_LD + kk];
#pragma unroll
            for (int i = 0; i < 4; i++) {
                acc[i][0] += p[i] * v4.x;
                acc[i][1] += p[i] * v4.y;
                acc[i][2] += p[i] * v4.z;
                acc[i][3] += p[i] * v4.w;
            }
        }
    }

    // publish 1/l, then write out y[b, q, h*64 + d]
    if (tid < BQ) row_linv[tid] = 1.f / l_run;
    __syncthreads();

    float* ybase = y + (size_t)b * SEQ * CMODEL + h * DHEAD;
#pragma unroll
    for (int i = 0; i < 4; i++) {
        int r = ty * 4 + i;
        float inv = row_linv[r];
        float4 o;
        o.x = acc[i][0] * inv;
        o.y = acc[i][1] * inv;
        o.z = acc[i][2] * inv;
        o.w = acc[i][3] * inv;
        *(float4*)&ybase[(size_t)(q0 + r) * CMODEL + tx * 4] = o;
    }
}

// ---------------------------------------------------------------------------
// Launch
// ---------------------------------------------------------------------------
extern "C" void kernel_launch(void* const* d_in, const int* in_sizes, int n_in,
                              void* d_out, int out_size)
{
    const float* x     = (const float*)d_in[0];   // [2,2048,1024]
    const float* w_qkv = (const float*)d_in[1];   // [1024,3072]
    const float* b_qkv = (const float*)d_in[2];   // [3072]
    const float* w_out = (const float*)d_in[3];   // [1024,1024]
    const float* b_out = (const float*)d_in[4];   // [1024]
    // d_in[5] = attn_mask (causal tril) — structure known, unused.

    float* qkv = nullptr;
    float* yy  = nullptr;
    cudaGetSymbolAddress((void**)&qkv, g_qkv);
    cudaGetSymbolAddress((void**)&yy,  g_y);

    float* out = (float*)d_out;

    // 1) QKV projection: [4096,1024] @ [1024,3072] + b
    {
        dim3 grid(QKV_N / BN, MROWS / BM);   // (24, 32)
        sgemm_bias_kernel<<<grid, 256>>>(x, w_qkv, b_qkv, qkv,
                                         MROWS, QKV_N, CMODEL);
    }
    // 2) causal flash attention
    {
        dim3 grid(SEQ / BQ, BATCH * NHEADS); // (32, 32)
        attn_kernel<<<grid, 256>>>(qkv, yy);
    }
    // 3) output projection: [4096,1024] @ [1024,1024] + b
    {
        dim3 grid(CMODEL / BN, MROWS / BM);  // (8, 32)
        sgemm_bias_kernel<<<grid, 256>>>(yy, w_out, b_out, out,
                                         MROWS, CMODEL, CMODEL);
    }
}

// round 2
// speedup vs baseline: 1.4120x; 1.4120x over previous
#include <cuda_runtime.h>
#include <cuda_bf16.h>
#include <math_constants.h>
#include <cstdint>

// Problem constants
#define BATCH   2
#define SEQ     2048
#define CMODEL  1024
#define NHEADS  16
#define DHEAD   64
#define MROWS   (BATCH * SEQ)          // 4096
#define QKV_N   (3 * CMODEL)           // 3072

// Scratch (allocation-free rule: __device__ globals)
__device__ float g_qkv[(size_t)MROWS * QKV_N];   // [4096, 3072]  Q|K|V concat
__device__ float g_y[(size_t)MROWS * CMODEL];    // [4096, 1024]  attention out

// ---------------------------------------------------------------------------
// TF32 tensor-core GEMM with fused bias: C[M,N] = A[M,K] @ B[K,N] + bias[N]
// 128x128 block tile, BK=16, 256 threads (8 warps, 2x4), warp tile 64x32,
// mma.sync.m16n8k8.tf32. Double-buffered smem; fp32->tf32 rna at smem store.
// smem stride 136 (mod 32 banks = 8) => fragment loads are conflict-free.
// ---------------------------------------------------------------------------
#define BM 128
#define BN 128
#define BKK 16
#define LDA (BM + 8)   // 136
#define LDB (BN + 8)   // 136

__device__ __forceinline__ uint32_t f2tf32(float x) {
    uint32_t u;
    asm("cvt.rna.tf32.f32 %0, %1;" : "=r"(u) : "f"(x));
    return u;
}

__device__ __forceinline__ void mma_tf32(float acc[4], const uint32_t a[4],
                                         const uint32_t b[2]) {
    asm("mma.sync.aligned.m16n8k8.row.col.f32.tf32.tf32.f32 "
        "{%0,%1,%2,%3}, {%4,%5,%6,%7}, {%8,%9}, {%0,%1,%2,%3};"
        : "+f"(acc[0]), "+f"(acc[1]), "+f"(acc[2]), "+f"(acc[3])
        : "r"(a[0]), "r"(a[1]), "r"(a[2]), "r"(a[3]), "r"(b[0]), "r"(b[1]));
}

__global__ __launch_bounds__(256, 1)
void tf32_gemm_bias(const float* __restrict__ A,
                    const float* __restrict__ B,
                    const float* __restrict__ bias,
                    float* __restrict__ C,
                    int M, int N, int K)
{
    __shared__ uint32_t As[2][BKK][LDA];   // transposed A tile: As[k][m]
    __shared__ uint32_t Bs[2][BKK][LDB];   // Bs[k][n]

    const int tid  = threadIdx.x;
    const int warp = tid >> 5;
    const int lane = tid & 31;
    const int gid  = lane >> 2;   // 0..7
    const int tig  = lane & 3;    // 0..3
    const int warpRow = (warp & 1) * 64;   // 2 warps in M
    const int warpCol = (warp >> 1) * 32;  // 4 warps in N
    const int rowBase = blockIdx.y * BM;
    const int colBase = blockIdx.x * BN;

    float acc[4][4][4];
#pragma unroll
    for (int mi = 0; mi < 4; mi++)
#pragma unroll
        for (int ni = 0; ni < 4; ni++)
#pragma unroll
            for (int r = 0; r < 4; r++) acc[mi][ni][r] = 0.f;

    // ---- load stage 0 ----
#pragma unroll
    for (int i = 0; i < 2; i++) {
        int idx = tid + i * 256;
        int r  = idx >> 2;      // 0..127
        int c4 = idx & 3;       // 0..3
        float4 a = *(const float4*)&A[(size_t)(rowBase + r) * K + c4 * 4];
        As[0][c4 * 4 + 0][r] = f2tf32(a.x);
        As[0][c4 * 4 + 1][r] = f2tf32(a.y);
        As[0][c4 * 4 + 2][r] = f2tf32(a.z);
        As[0][c4 * 4 + 3][r] = f2tf32(a.w);
    }
#pragma unroll
    for (int i = 0; i < 2; i++) {
        int idx = tid + i * 256;
        int r  = idx >> 5;      // 0..15
        int c4 = idx & 31;      // 0..31
        float4 b = *(const float4*)&B[(size_t)r * N + colBase + c4 * 4];
        uint4 ub;
        ub.x = f2tf32(b.x); ub.y = f2tf32(b.y);
        ub.z = f2tf32(b.z); ub.w = f2tf32(b.w);
        *(uint4*)&Bs[0][r][c4 * 4] = ub;
    }
    __syncthreads();

    int s = 0;
    for (int k0 = 0; k0 < K; k0 += BKK) {
        const bool nxt = (k0 + BKK) < K;
        float4 pa[2], pb[2];
        if (nxt) {
#pragma unroll
            for (int i = 0; i < 2; i++) {
                int idx = tid + i * 256;
                int r  = idx >> 2;
                int c4 = idx & 3;
                pa[i] = *(const float4*)&A[(size_t)(rowBase + r) * K + k0 + BKK + c4 * 4];
            }
#pragma unroll
            for (int i = 0; i < 2; i++) {
                int idx = tid + i * 256;
                int r  = idx >> 5;
                int c4 = idx & 31;
                pb[i] = *(const float4*)&B[(size_t)(k0 + BKK + r) * N + colBase + c4 * 4];
            }
        }

        // ---- compute on stage s (two k8-steps) ----
#pragma unroll
        for (int k8 = 0; k8 < BKK; k8 += 8) {
            uint32_t af[4][4], bf[4][2];
#pragma unroll
            for (int mi = 0; mi < 4; mi++) {
                int row = warpRow + mi * 16 + gid;
                af[mi][0] = As[s][k8 + tig    ][row];
                af[mi][1] = As[s][k8 + tig    ][row + 8];
                af[mi][2] = As[s][k8 + tig + 4][row];
                af[mi][3] = As[s][k8 + tig + 4][row + 8];
            }
#pragma unroll
            for (int ni = 0; ni < 4; ni++) {
                int col = warpCol + ni * 8 + gid;
                bf[ni][0] = Bs[s][k8 + tig    ][col];
                bf[ni][1] = Bs[s][k8 + tig + 4][col];
            }
#pragma unroll
            for (int mi = 0; mi < 4; mi++)
#pragma unroll
                for (int ni = 0; ni < 4; ni++)
                    mma_tf32(acc[mi][ni], af[mi], bf[ni]);
        }

        if (nxt) {
#pragma unroll
            for (int i = 0; i < 2; i++) {
                int idx = tid + i * 256;
                int r  = idx >> 2;
                int c4 = idx & 3;
                As[s ^ 1][c4 * 4 + 0][r] = f2tf32(pa[i].x);
                As[s ^ 1][c4 * 4 + 1][r] = f2tf32(pa[i].y);
                As[s ^ 1][c4 * 4 + 2][r] = f2tf32(pa[i].z);
                As[s ^ 1][c4 * 4 + 3][r] = f2tf32(pa[i].w);
            }
#pragma unroll
            for (int i = 0; i < 2; i++) {
                int idx = tid + i * 256;
                int r  = idx >> 5;
                int c4 = idx & 31;
                uint4 ub;
                ub.x = f2tf32(pb[i].x); ub.y = f2tf32(pb[i].y);
                ub.z = f2tf32(pb[i].z); ub.w = f2tf32(pb[i].w);
                *(uint4*)&Bs[s ^ 1][r][c4 * 4] = ub;
            }
            __syncthreads();
            s ^= 1;
        }
    }

    // ---- epilogue: bias + store ----
#pragma unroll
    for (int mi = 0; mi < 4; mi++) {
        int r0 = rowBase + warpRow + mi * 16 + gid;
#pragma unroll
        for (int ni = 0; ni < 4; ni++) {
            int c = colBase + warpCol + ni * 8 + tig * 2;
            float2 bz = *(const float2*)&bias[c];
            float2 o0, o1;
            o0.x = acc[mi][ni][0] + bz.x;
            o0.y = acc[mi][ni][1] + bz.y;
            o1.x = acc[mi][ni][2] + bz.x;
            o1.y = acc[mi][ni][3] + bz.y;
            *(float2*)&C[(size_t)r0 * N + c]       = o0;
            *(float2*)&C[(size_t)(r0 + 8) * N + c] = o1;
        }
    }
}

// ---------------------------------------------------------------------------
// Fused causal flash attention, fp32 (unchanged from R1 — known correct).
// ---------------------------------------------------------------------------
#define BQ 64
#define BKT 32
#define KS_LD 65
#define SS_LD 33

__global__ __launch_bounds__(256, 2)
void attn_kernel(const float* __restrict__ qkv, float* __restrict__ y)
{
    __shared__ float Qs[BQ * DHEAD];
    __shared__ float Ks[BKT * KS_LD];
    __shared__ float Vs[BKT * DHEAD];
    __shared__ float Ss[BQ * SS_LD];
    __shared__ float row_alpha[BQ];
    __shared__ float row_linv[BQ];

    const int tid = threadIdx.x;
    const int q0  = blockIdx.x * BQ;
    const int bh  = blockIdx.y;
    const int b   = bh >> 4;
    const int h   = bh & 15;

    const float* base = qkv + (size_t)b * SEQ * QKV_N + h * DHEAD;

#pragma unroll
    for (int i = 0; i < 4; i++) {
        int idx = tid + i * 256;
        int r  = idx >> 4;
        int c4 = idx & 15;
        float4 v = *(const float4*)&base[(size_t)(q0 + r) * QKV_N + c4 * 4];
        *(float4*)&Qs[r * DHEAD + c4 * 4] = v;
    }

    const int ty = tid >> 4;
    const int tx = tid & 15;

    float acc[4][4];
#pragma unroll
    for (int i = 0; i < 4; i++)
#pragma unroll
        for (int j = 0; j < 4; j++) acc[i][j] = 0.f;

    float m_run = -CUDART_INF_F;
    float l_run = 0.f;

    const int nkt = (q0 >> 5) + 2;

    for (int kt = 0; kt < nkt; kt++) {
        const int k0 = kt * BKT;
        __syncthreads();

#pragma unroll
        for (int i = 0; i < 2; i++) {
            int idx = tid + i * 256;
            int r  = idx >> 4;
            int c4 = idx & 15;
            float4 kv = *(const float4*)&base[CMODEL + (size_t)(k0 + r) * QKV_N + c4 * 4];
            Ks[r * KS_LD + c4 * 4 + 0] = kv.x;
            Ks[r * KS_LD + c4 * 4 + 1] = kv.y;
            Ks[r * KS_LD + c4 * 4 + 2] = kv.z;
            Ks[r * KS_LD + c4 * 4 + 3] = kv.w;
            float4 vv = *(const float4*)&base[2 * CMODEL + (size_t)(k0 + r) * QKV_N + c4 * 4];
            *(float4*)&Vs[r * DHEAD + c4 * 4] = vv;
        }
        __syncthreads();

        float s[4][2];
#pragma unroll
        for (int i = 0; i < 4; i++) { s[i][0] = 0.f; s[i][1] = 0.f; }
#pragma unroll 8
        for (int k = 0; k < DHEAD; k++) {
            float qa[4], kb[2];
#pragma unroll
            for (int i = 0; i < 4; i++) qa[i] = Qs[(ty * 4 + i) * DHEAD + k];
            kb[0] = Ks[(tx * 2 + 0) * KS_LD + k];
            kb[1] = Ks[(tx * 2 + 1) * KS_LD + k];
#pragma unroll
            for (int i = 0; i < 4; i++) {
                s[i][0] += qa[i] * kb[0];
                s[i][1] += qa[i] * kb[1];
            }
        }
#pragma unroll
        for (int i = 0; i < 4; i++) {
            int r = ty * 4 + i;
#pragma unroll
            for (int j = 0; j < 2; j++) {
                int c = tx * 2 + j;
                bool valid = (k0 + c) <= (q0 + r);
                Ss[r * SS_LD + c] = valid ? s[i][j] * 0.125f : -CUDART_INF_F;
            }
        }
        __syncthreads();

        if (tid < BQ) {
            const int r = tid;
            float tm = -CUDART_INF_F;
#pragma unroll 8
            for (int j = 0; j < BKT; j++) tm = fmaxf(tm, Ss[r * SS_LD + j]);
            float mn = fmaxf(m_run, tm);
            float al = __expf(m_run - mn);
            float sum = 0.f;
#pragma unroll 8
            for (int j = 0; j < BKT; j++) {
                float p = __expf(Ss[r * SS_LD + j] - mn);
                Ss[r * SS_LD + j] = p;
                sum += p;
            }
            l_run = al * l_run + sum;
            m_run = mn;
            row_alpha[r] = al;
        }
        __syncthreads();

        float alr[4];
#pragma unroll
        for (int i = 0; i < 4; i++) {
            alr[i] = row_alpha[ty * 4 + i];
#pragma unroll
            for (int j = 0; j < 4; j++) acc[i][j] *= alr[i];
        }
#pragma unroll 4
        for (int kk = 0; kk < BKT; kk++) {
            float4 v4 = *(const float4*)&Vs[kk * DHEAD + tx * 4];
            float p[4];
#pragma unroll
            for (int i = 0; i < 4; i++) p[i] = Ss[(ty * 4 + i) * SS_LD + kk];
#pragma unroll
            for (int i = 0; i < 4; i++) {
                acc[i][0] += p[i] * v4.x;
                acc[i][1] += p[i] * v4.y;
                acc[i][2] += p[i] * v4.z;
                acc[i][3] += p[i] * v4.w;
            }
        }
    }

    if (tid < BQ) row_linv[tid] = 1.f / l_run;
    __syncthreads();

    float* ybase = y + (size_t)b * SEQ * CMODEL + h * DHEAD;
#pragma unroll
    for (int i = 0; i < 4; i++) {
        int r = ty * 4 + i;
        float inv = row_linv[r];
        float4 o;
        o.x = acc[i][0] * inv;
        o.y = acc[i][1] * inv;
        o.z = acc[i][2] * inv;
        o.w = acc[i][3] * inv;
        *(float4*)&ybase[(size_t)(q0 + r) * CMODEL + tx * 4] = o;
    }
}

// ---------------------------------------------------------------------------
// Launch
// ---------------------------------------------------------------------------
extern "C" void kernel_launch(void* const* d_in, const int* in_sizes, int n_in,
                              void* d_out, int out_size)
{
    const float* x     = (const float*)d_in[0];
    const float* w_qkv = (const float*)d_in[1];
    const float* b_qkv = (const float*)d_in[2];
    const float* w_out = (const float*)d_in[3];
    const float* b_out = (const float*)d_in[4];

    float* qkv = nullptr;
    float* yy  = nullptr;
    cudaGetSymbolAddress((void**)&qkv, g_qkv);
    cudaGetSymbolAddress((void**)&yy,  g_y);

    float* out = (float*)d_out;

    // 1) QKV projection: [4096,1024] @ [1024,3072] + b  (tf32 tensor cores)
    {
        dim3 grid(QKV_N / BN, MROWS / BM);   // (24, 32)
        tf32_gemm_bias<<<grid, 256>>>(x, w_qkv, b_qkv, qkv,
                                      MROWS, QKV_N, CMODEL);
    }
    // 2) causal flash attention (fp32)
    {
        dim3 grid(SEQ / BQ, BATCH * NHEADS); // (32, 32)
        attn_kernel<<<grid, 256>>>(qkv, yy);
    }
    // 3) output projection: [4096,1024] @ [1024,1024] + b (tf32 tensor cores)
    {
        dim3 grid(CMODEL / BN, MROWS / BM);  // (8, 32)
        tf32_gemm_bias<<<grid, 256>>>(yy, w_out, b_out, out,
                                      MROWS, CMODEL, CMODEL);
    }
}

// round 7
// speedup vs baseline: 1.6958x; 1.2010x over previous
#include <cuda_runtime.h>
#include <cuda_bf16.h>
#include <math_constants.h>
#include <cstdint>

// Problem constants
#define BATCH   2
#define SEQ     2048
#define CMODEL  1024
#define NHEADS  16
#define DHEAD   64
#define MROWS   (BATCH * SEQ)          // 4096
#define QKV_N   (3 * CMODEL)           // 3072

// Scratch (allocation-free rule: __device__ globals)
__device__ float g_qkv[(size_t)MROWS * QKV_N];   // [4096, 3072]  Q|K|V concat
__device__ float g_y[(size_t)MROWS * CMODEL];    // [4096, 1024]  attention out

// ---------------------------------------------------------------------------
// Shared mma helpers (fragment layout validated by R2 passing GEMM)
// ---------------------------------------------------------------------------
__device__ __forceinline__ uint32_t f2tf32(float x) {
    uint32_t u;
    asm("cvt.rna.tf32.f32 %0, %1;" : "=r"(u) : "f"(x));
    return u;
}

// 3xTF32 split: x ~= hi + lo, each tf32-representable; error ~2^-22
__device__ __forceinline__ void split_tf32(float x, uint32_t& hi, uint32_t& lo) {
    uint32_t h;
    asm("cvt.rna.tf32.f32 %0, %1;" : "=r"(h) : "f"(x));
    float r = x - __uint_as_float(h);
    uint32_t l;
    asm("cvt.rna.tf32.f32 %0, %1;" : "=r"(l) : "f"(r));
    hi = h; lo = l;
}

__device__ __forceinline__ void mma_tf32(float acc[4], const uint32_t a[4],
                                         const uint32_t b[2]) {
    asm("mma.sync.aligned.m16n8k8.row.col.f32.tf32.tf32.f32 "
        "{%0,%1,%2,%3}, {%4,%5,%6,%7}, {%8,%9}, {%0,%1,%2,%3};"
        : "+f"(acc[0]), "+f"(acc[1]), "+f"(acc[2]), "+f"(acc[3])
        : "r"(a[0]), "r"(a[1]), "r"(a[2]), "r"(a[3]), "r"(b[0]), "r"(b[1]));
}

// ---------------------------------------------------------------------------
// TF32 tensor-core GEMM with fused bias (unchanged from R2 — known good)
// ---------------------------------------------------------------------------
#define BM 128
#define BN 128
#define BKK 16
#define LDA (BM + 8)
#define LDB (BN + 8)

__global__ __launch_bounds__(256, 1)
void tf32_gemm_bias(const float* __restrict__ A,
                    const float* __restrict__ B,
                    const float* __restrict__ bias,
                    float* __restrict__ C,
                    int M, int N, int K)
{
    __shared__ uint32_t As[2][BKK][LDA];
    __shared__ uint32_t Bs[2][BKK][LDB];

    const int tid  = threadIdx.x;
    const int warp = tid >> 5;
    const int lane = tid & 31;
    const int gid  = lane >> 2;
    const int tig  = lane & 3;
    const int warpRow = (warp & 1) * 64;
    const int warpCol = (warp >> 1) * 32;
    const int rowBase = blockIdx.y * BM;
    const int colBase = blockIdx.x * BN;

    float acc[4][4][4];
#pragma unroll
    for (int mi = 0; mi < 4; mi++)
#pragma unroll
        for (int ni = 0; ni < 4; ni++)
#pragma unroll
            for (int r = 0; r < 4; r++) acc[mi][ni][r] = 0.f;

#pragma unroll
    for (int i = 0; i < 2; i++) {
        int idx = tid + i * 256;
        int r  = idx >> 2;
        int c4 = idx & 3;
        float4 a = *(const float4*)&A[(size_t)(rowBase + r) * K + c4 * 4];
        As[0][c4 * 4 + 0][r] = f2tf32(a.x);
        As[0][c4 * 4 + 1][r] = f2tf32(a.y);
        As[0][c4 * 4 + 2][r] = f2tf32(a.z);
        As[0][c4 * 4 + 3][r] = f2tf32(a.w);
    }
#pragma unroll
    for (int i = 0; i < 2; i++) {
        int idx = tid + i * 256;
        int r  = idx >> 5;
        int c4 = idx & 31;
        float4 b = *(const float4*)&B[(size_t)r * N + colBase + c4 * 4];
        uint4 ub;
        ub.x = f2tf32(b.x); ub.y = f2tf32(b.y);
        ub.z = f2tf32(b.z); ub.w = f2tf32(b.w);
        *(uint4*)&Bs[0][r][c4 * 4] = ub;
    }
    __syncthreads();

    int s = 0;
    for (int k0 = 0; k0 < K; k0 += BKK) {
        const bool nxt = (k0 + BKK) < K;
        float4 pa[2], pb[2];
        if (nxt) {
#pragma unroll
            for (int i = 0; i < 2; i++) {
                int idx = tid + i * 256;
                int r  = idx >> 2;
                int c4 = idx & 3;
                pa[i] = *(const float4*)&A[(size_t)(rowBase + r) * K + k0 + BKK + c4 * 4];
            }
#pragma unroll
            for (int i = 0; i < 2; i++) {
                int idx = tid + i * 256;
                int r  = idx >> 5;
                int c4 = idx & 31;
                pb[i] = *(const float4*)&B[(size_t)(k0 + BKK + r) * N + colBase + c4 * 4];
            }
        }

#pragma unroll
        for (int k8 = 0; k8 < BKK; k8 += 8) {
            uint32_t af[4][4], bf[4][2];
#pragma unroll
            for (int mi = 0; mi < 4; mi++) {
                int row = warpRow + mi * 16 + gid;
                af[mi][0] = As[s][k8 + tig    ][row];
                af[mi][1] = As[s][k8 + tig    ][row + 8];
                af[mi][2] = As[s][k8 + tig + 4][row];
                af[mi][3] = As[s][k8 + tig + 4][row + 8];
            }
#pragma unroll
            for (int ni = 0; ni < 4; ni++) {
                int col = warpCol + ni * 8 + gid;
                bf[ni][0] = Bs[s][k8 + tig    ][col];
                bf[ni][1] = Bs[s][k8 + tig + 4][col];
            }
#pragma unroll
            for (int mi = 0; mi < 4; mi++)
#pragma unroll
                for (int ni = 0; ni < 4; ni++)
                    mma_tf32(acc[mi][ni], af[mi], bf[ni]);
        }

        if (nxt) {
#pragma unroll
            for (int i = 0; i < 2; i++) {
                int idx = tid + i * 256;
                int r  = idx >> 2;
                int c4 = idx & 3;
                As[s ^ 1][c4 * 4 + 0][r] = f2tf32(pa[i].x);
                As[s ^ 1][c4 * 4 + 1][r] = f2tf32(pa[i].y);
                As[s ^ 1][c4 * 4 + 2][r] = f2tf32(pa[i].z);
                As[s ^ 1][c4 * 4 + 3][r] = f2tf32(pa[i].w);
            }
#pragma unroll
            for (int i = 0; i < 2; i++) {
                int idx = tid + i * 256;
                int r  = idx >> 5;
                int c4 = idx & 31;
                uint4 ub;
                ub.x = f2tf32(pb[i].x); ub.y = f2tf32(pb[i].y);
                ub.z = f2tf32(pb[i].z); ub.w = f2tf32(pb[i].w);
                *(uint4*)&Bs[s ^ 1][r][c4 * 4] = ub;
            }
            __syncthreads();
            s ^= 1;
        }
    }

#pragma unroll
    for (int mi = 0; mi < 4; mi++) {
        int r0 = rowBase + warpRow + mi * 16 + gid;
#pragma unroll
        for (int ni = 0; ni < 4; ni++) {
            int c = colBase + warpCol + ni * 8 + tig * 2;
            float2 bz = *(const float2*)&bias[c];
            float2 o0, o1;
            o0.x = acc[mi][ni][0] + bz.x;
            o0.y = acc[mi][ni][1] + bz.y;
            o1.x = acc[mi][ni][2] + bz.x;
            o1.y = acc[mi][ni][3] + bz.y;
            *(float2*)&C[(size_t)r0 * N + c]       = o0;
            *(float2*)&C[(size_t)(r0 + 8) * N + c] = o1;
        }
    }
}

// ---------------------------------------------------------------------------
// Tensor-core causal flash attention (3xTF32 for QK^T and PV).
// STATIC smem only (44,032 B < 48KB): no dynamic smem, no cudaFuncSetAttribute.
// 128 threads / 4 warps. BQ=64 (warp w owns rows 16w..16w+15), key tile 32.
// P buffer ALIASES the K buffer (K read only in S phase; extra __syncthreads
// orders the handoff). Strides 68 (==4 mod 32) / 72 (==8 mod 32) keep every
// fragment access conflict-free.
// ---------------------------------------------------------------------------
#define ABQ 64
#define ABK 32
#define QLD 68
#define KLD 68
#define VLD 72
#define PLD 68

__global__ __launch_bounds__(128)
void attn_tc_kernel(const float* __restrict__ qkv, float* __restrict__ y)
{
    __shared__ float Qs[ABQ * QLD];   // [64][68]
    __shared__ float Us[ABQ * PLD];   // union: Ks [32][68] then Ps [64][68]
    __shared__ float Vs[ABK * VLD];   // [32][72]

    const int tid  = threadIdx.x;
    const int warp = tid >> 5;     // 0..3
    const int lane = tid & 31;
    const int gid  = lane >> 2;    // 0..7
    const int tig  = lane & 3;     // 0..3
    const int w16  = warp * 16;
    const int q0   = blockIdx.x * ABQ;
    const int bh   = blockIdx.y;
    const int b    = bh >> 4;
    const int h    = bh & 15;

    const float* base = qkv + (size_t)b * SEQ * QKV_N + h * DHEAD;
    const float* kb   = base + CMODEL;
    const float* vb   = base + 2 * CMODEL;

    // Load Q tile: 64 rows x 64 cols = 1024 float4, 128 threads x 8
#pragma unroll
    for (int i = 0; i < 8; i++) {
        int idx = tid + i * 128;
        int r  = idx >> 4;
        int c4 = idx & 15;
        float4 t = *(const float4*)&base[(size_t)(q0 + r) * QKV_N + c4 * 4];
        *(float4*)&Qs[r * QLD + c4 * 4] = t;
    }

    float yacc[8][4];
#pragma unroll
    for (int nt = 0; nt < 8; nt++)
#pragma unroll
        for (int r = 0; r < 4; r++) yacc[nt][r] = 0.f;

    float mprev[2] = {-CUDART_INF_F, -CUDART_INF_F};
    float lrun[2]  = {0.f, 0.f};

    const int nkt   = 2 * blockIdx.x + 2;   // key tiles of 32 covering <= q0+63
    const int rowg0 = q0 + w16 + gid;
    const float SC  = 0.125f;

    for (int kt = 0; kt < nkt; kt++) {
        const int k0 = kt * ABK;
        const bool partial = (kt >= 2 * (int)blockIdx.x);
        __syncthreads();   // prior iter's P/V readers done before overwrite

        // Load K (into union) and V tiles: 32 rows x 64 cols = 512 float4 each
#pragma unroll
        for (int i = 0; i < 4; i++) {
            int idx = tid + i * 128;
            int r  = idx >> 4;
            int c4 = idx & 15;
            float4 tk = *(const float4*)&kb[(size_t)(k0 + r) * QKV_N + c4 * 4];
            *(float4*)&Us[r * KLD + c4 * 4] = tk;
            float4 tv = *(const float4*)&vb[(size_t)(k0 + r) * QKV_N + c4 * 4];
            *(float4*)&Vs[r * VLD + c4 * 4] = tv;
        }
        __syncthreads();

        // ---- S = Q K^T  (3xTF32), 4 n-tiles of 8 keys ----
        float sacc[4][4];
#pragma unroll
        for (int ni = 0; ni < 4; ni++)
#pragma unroll
            for (int r = 0; r < 4; r++) sacc[ni][r] = 0.f;

#pragma unroll
        for (int s8 = 0; s8 < 8; s8++) {
            const int kk = s8 * 8;
            float a0 = Qs[(w16 + gid)     * QLD + kk + tig];
            float a1 = Qs[(w16 + gid + 8) * QLD + kk + tig];
            float a2 = Qs[(w16 + gid)     * QLD + kk + tig + 4];
            float a3 = Qs[(w16 + gid + 8) * QLD + kk + tig + 4];
            uint32_t ah[4], al[4];
            split_tf32(a0, ah[0], al[0]);
            split_tf32(a1, ah[1], al[1]);
            split_tf32(a2, ah[2], al[2]);
            split_tf32(a3, ah[3], al[3]);
#pragma unroll
            for (int ni = 0; ni < 4; ni++) {
                float b0 = Us[(ni * 8 + gid) * KLD + kk + tig];
                float b1 = Us[(ni * 8 + gid) * KLD + kk + tig + 4];
                uint32_t bh2[2], bl2[2];
                split_tf32(b0, bh2[0], bl2[0]);
                split_tf32(b1, bh2[1], bl2[1]);
                mma_tf32(sacc[ni], ah, bl2);
                mma_tf32(sacc[ni], al, bh2);
                mma_tf32(sacc[ni], ah, bh2);
            }
        }
        __syncthreads();   // ALL warps done reading Ks before P overwrites it

        // ---- online softmax (rows gid and gid+8, replicated in quad) ----
        float alpha[2];
#pragma unroll
        for (int hf = 0; hf < 2; hf++) {
            const int rowg = rowg0 + 8 * hf;
            float mt = -CUDART_INF_F;
#pragma unroll
            for (int ni = 0; ni < 4; ni++) {
#pragma unroll
                for (int c = 0; c < 2; c++) {
                    float v = sacc[ni][2 * hf + c] * SC;
                    if (partial) {
                        int key = k0 + ni * 8 + 2 * tig + c;
                        if (key > rowg) v = -CUDART_INF_F;
                    }
                    sacc[ni][2 * hf + c] = v;
                    mt = fmaxf(mt, v);
                }
            }
            mt = fmaxf(mt, __shfl_xor_sync(0xffffffffu, mt, 1));
            mt = fmaxf(mt, __shfl_xor_sync(0xffffffffu, mt, 2));
            float mn = fmaxf(mprev[hf], mt);
            float al2 = __expf(mprev[hf] - mn);
            float lsum = 0.f;
#pragma unroll
            for (int ni = 0; ni < 4; ni++) {
                float p0 = __expf(sacc[ni][2 * hf + 0] - mn);
                float p1 = __expf(sacc[ni][2 * hf + 1] - mn);
                lsum += p0 + p1;
                *(float2*)&Us[(w16 + gid + 8 * hf) * PLD + ni * 8 + 2 * tig] =
                    make_float2(p0, p1);
            }
            lsum += __shfl_xor_sync(0xffffffffu, lsum, 1);
            lsum += __shfl_xor_sync(0xffffffffu, lsum, 2);
            lrun[hf] = al2 * lrun[hf] + lsum;
            mprev[hf] = mn;
            alpha[hf] = al2;
        }
        // rescale accumulators
#pragma unroll
        for (int nt = 0; nt < 8; nt++) {
            yacc[nt][0] *= alpha[0];
            yacc[nt][1] *= alpha[0];
            yacc[nt][2] *= alpha[1];
            yacc[nt][3] *= alpha[1];
        }
        __syncwarp();   // P stores visible to this warp's fragment loads

        // ---- O += P V  (3xTF32); each warp reads only its OWN P rows ----
#pragma unroll
        for (int s8 = 0; s8 < 4; s8++) {
            const int kk = s8 * 8;
            float a0 = Us[(w16 + gid)     * PLD + kk + tig];
            float a1 = Us[(w16 + gid + 8) * PLD + kk + tig];
            float a2 = Us[(w16 + gid)     * PLD + kk + tig + 4];
            float a3 = Us[(w16 + gid + 8) * PLD + kk + tig + 4];
            uint32_t ah[4], al[4];
            split_tf32(a0, ah[0], al[0]);
            split_tf32(a1, ah[1], al[1]);
            split_tf32(a2, ah[2], al[2]);
            split_tf32(a3, ah[3], al[3]);
#pragma unroll
            for (int nt = 0; nt < 8; nt++) {
                float b0 = Vs[(kk + tig)     * VLD + nt * 8 + gid];
                float b1 = Vs[(kk + tig + 4) * VLD + nt * 8 + gid];
                uint32_t bh2[2], bl2[2];
                split_tf32(b0, bh2[0], bl2[0]);
                split_tf32(b1, bh2[1], bl2[1]);
                mma_tf32(yacc[nt], ah, bl2);
                mma_tf32(yacc[nt], al, bh2);
                mma_tf32(yacc[nt], ah, bh2);
            }
        }
    }

    // ---- epilogue: divide by l, store ----
    float linv0 = 1.f / lrun[0];
    float linv1 = 1.f / lrun[1];
    float* yb = y + (size_t)b * SEQ * CMODEL + h * DHEAD;
#pragma unroll
    for (int nt = 0; nt < 8; nt++) {
        int c = nt * 8 + 2 * tig;
        float2 o0, o1;
        o0.x = yacc[nt][0] * linv0;
        o0.y = yacc[nt][1] * linv0;
        o1.x = yacc[nt][2] * linv1;
        o1.y = yacc[nt][3] * linv1;
        *(float2*)&yb[(size_t)(rowg0)     * CMODEL + c] = o0;
        *(float2*)&yb[(size_t)(rowg0 + 8) * CMODEL + c] = o1;
    }
}

// ---------------------------------------------------------------------------
// Launch
// ---------------------------------------------------------------------------
extern "C" void kernel_launch(void* const* d_in, const int* in_sizes, int n_in,
                              void* d_out, int out_size)
{
    const float* x     = (const float*)d_in[0];
    const float* w_qkv = (const float*)d_in[1];
    const float* b_qkv = (const float*)d_in[2];
    const float* w_out = (const float*)d_in[3];
    const float* b_out = (const float*)d_in[4];

    float* qkv = nullptr;
    float* yy  = nullptr;
    cudaGetSymbolAddress((void**)&qkv, g_qkv);
    cudaGetSymbolAddress((void**)&yy,  g_y);

    float* out = (float*)d_out;

    // 1) QKV projection (tf32 tensor cores)
    {
        dim3 grid(QKV_N / BN, MROWS / BM);   // (24, 32)
        tf32_gemm_bias<<<grid, 256>>>(x, w_qkv, b_qkv, qkv,
                                      MROWS, QKV_N, CMODEL);
    }
    // 2) causal flash attention (3xTF32 tensor cores, static smem)
    {
        dim3 grid(SEQ / ABQ, BATCH * NHEADS);   // (32, 32)
        attn_tc_kernel<<<grid, 128>>>(qkv, yy);
    }
    // 3) output projection (tf32 tensor cores)
    {
        dim3 grid(CMODEL / BN, MROWS / BM);  // (8, 32)
        tf32_gemm_bias<<<grid, 256>>>(yy, w_out, b_out, out,
                                      MROWS, CMODEL, CMODEL);
    }
}

// round 9
// speedup vs baseline: 2.5642x; 1.5120x over previous
#include <cuda_runtime.h>
#include <cuda_bf16.h>
#include <math_constants.h>
#include <cstdint>

// Problem constants
#define BATCH   2
#define SEQ     2048
#define CMODEL  1024
#define NHEADS  16
#define DHEAD   64
#define MROWS   (BATCH * SEQ)          // 4096
#define QKV_N   (3 * CMODEL)           // 3072

// Scratch (allocation-free rule: __device__ globals)
__device__ float g_qkv[(size_t)MROWS * QKV_N];    // [4096, 3072] Q|K|V (fp32)
__device__ float g_y[(size_t)MROWS * CMODEL];     // [4096, 1024] attn out (tf32-rounded)
__device__ float g_xc[(size_t)MROWS * CMODEL];    // x, tf32-rounded
__device__ float g_wqkvc[(size_t)CMODEL * QKV_N]; // w_qkv, tf32-rounded
__device__ float g_woutc[(size_t)CMODEL * CMODEL];// w_out, tf32-rounded

// ---------------------------------------------------------------------------
// Helpers
// ---------------------------------------------------------------------------
__device__ __forceinline__ uint32_t f2tf32(float x) {
    uint32_t u;
    asm("cvt.rna.tf32.f32 %0, %1;" : "=r"(u) : "f"(x));
    return u;
}
__device__ __forceinline__ float rtf(float x) {
    return __uint_as_float(f2tf32(x));
}

// 3xTF32 split: x ~= hi + lo, each tf32-representable; error ~2^-22
__device__ __forceinline__ void split_tf32(float x, uint32_t& hi, uint32_t& lo) {
    uint32_t h;
    asm("cvt.rna.tf32.f32 %0, %1;" : "=r"(h) : "f"(x));
    float r = x - __uint_as_float(h);
    uint32_t l;
    asm("cvt.rna.tf32.f32 %0, %1;" : "=r"(l) : "f"(r));
    hi = h; lo = l;
}

__device__ __forceinline__ void mma_tf32(float acc[4], const uint32_t a[4],
                                         const uint32_t b[2]) {
    asm("mma.sync.aligned.m16n8k8.row.col.f32.tf32.tf32.f32 "
        "{%0,%1,%2,%3}, {%4,%5,%6,%7}, {%8,%9}, {%0,%1,%2,%3};"
        : "+f"(acc[0]), "+f"(acc[1]), "+f"(acc[2]), "+f"(acc[3])
        : "r"(a[0]), "r"(a[1]), "r"(a[2]), "r"(a[3]), "r"(b[0]), "r"(b[1]));
}

__device__ __forceinline__ void cp16(void* dst, const void* src) {
    uint32_t d = (uint32_t)__cvta_generic_to_shared(dst);
    asm volatile("cp.async.cg.shared.global [%0], [%1], 16;" :: "r"(d), "l"(src));
}
#define CP_COMMIT() asm volatile("cp.async.commit_group;")
#define CP_WAIT0()  asm volatile("cp.async.wait_group 0;")

// ---------------------------------------------------------------------------
// Elementwise tf32 rounding (pre-conversion). n divisible by 4.
// ---------------------------------------------------------------------------
__global__ void cvt_tf32_kernel(const float* __restrict__ in,
                                float* __restrict__ out, int n4)
{
    int i = blockIdx.x * blockDim.x + threadIdx.x;
    if (i < n4) {
        float4 v = ((const float4*)in)[i];
        float4 o;
        o.x = rtf(v.x); o.y = rtf(v.y); o.z = rtf(v.z); o.w = rtf(v.w);
        ((float4*)out)[i] = o;
    }
}

// ---------------------------------------------------------------------------
// TF32 GEMM, fused bias. Operands PRE-ROUNDED to tf32 (no cvt inside).
// 128x128 tile, BK=16, 256 threads, warp tile 64x32, cp.async double buffer.
// As[m][20]: 20 mod 32 = 20 -> A-frag lanes (gid rows, tig cols) conflict-free.
// Bs[k][136]: 136 mod 32 = 8 -> B-frag lanes conflict-free.
// ---------------------------------------------------------------------------
#define BM 128
#define BN 128
#define BKK 16
#define ALD 20
#define LDB 136

__global__ __launch_bounds__(256, 2)
void tf32_gemm_bias(const float* __restrict__ A,
                    const float* __restrict__ B,
                    const float* __restrict__ bias,
                    float* __restrict__ C,
                    int M, int N, int K)
{
    __shared__ float As[2][BM][ALD];
    __shared__ float Bs[2][BKK][LDB];

    const int tid  = threadIdx.x;
    const int warp = tid >> 5;
    const int lane = tid & 31;
    const int gid  = lane >> 2;
    const int tig  = lane & 3;
    const int warpRow = (warp & 1) * 64;
    const int warpCol = (warp >> 1) * 32;
    const int rowBase = blockIdx.y * BM;
    const int colBase = blockIdx.x * BN;

    float acc[4][4][4];
#pragma unroll
    for (int mi = 0; mi < 4; mi++)
#pragma unroll
        for (int ni = 0; ni < 4; ni++)
#pragma unroll
            for (int r = 0; r < 4; r++) acc[mi][ni][r] = 0.f;

    // ---- stage 0 ----
#pragma unroll
    for (int i = 0; i < 2; i++) {
        int idx = tid + i * 256;
        int r  = idx >> 2;
        int c4 = idx & 3;
        cp16(&As[0][r][c4 * 4], &A[(size_t)(rowBase + r) * K + c4 * 4]);
    }
#pragma unroll
    for (int i = 0; i < 2; i++) {
        int idx = tid + i * 256;
        int r  = idx >> 5;
        int c4 = idx & 31;
        cp16(&Bs[0][r][c4 * 4], &B[(size_t)r * N + colBase + c4 * 4]);
    }
    CP_COMMIT();
    CP_WAIT0();
    __syncthreads();

    int s = 0;
    for (int k0 = 0; k0 < K; k0 += BKK) {
        const bool nxt = (k0 + BKK) < K;
        if (nxt) {
#pragma unroll
            for (int i = 0; i < 2; i++) {
                int idx = tid + i * 256;
                int r  = idx >> 2;
                int c4 = idx & 3;
                cp16(&As[s ^ 1][r][c4 * 4],
                     &A[(size_t)(rowBase + r) * K + k0 + BKK + c4 * 4]);
            }
#pragma unroll
            for (int i = 0; i < 2; i++) {
                int idx = tid + i * 256;
                int r  = idx >> 5;
                int c4 = idx & 31;
                cp16(&Bs[s ^ 1][r][c4 * 4],
                     &B[(size_t)(k0 + BKK + r) * N + colBase + c4 * 4]);
            }
            CP_COMMIT();
        }

#pragma unroll
        for (int k8 = 0; k8 < BKK; k8 += 8) {
            uint32_t af[4][4], bf[4][2];
#pragma unroll
            for (int mi = 0; mi < 4; mi++) {
                int row = warpRow + mi * 16 + gid;
                af[mi][0] = __float_as_uint(As[s][row    ][k8 + tig]);
                af[mi][1] = __float_as_uint(As[s][row + 8][k8 + tig]);
                af[mi][2] = __float_as_uint(As[s][row    ][k8 + tig + 4]);
                af[mi][3] = __float_as_uint(As[s][row + 8][k8 + tig + 4]);
            }
#pragma unroll
            for (int ni = 0; ni < 4; ni++) {
                int col = warpCol + ni * 8 + gid;
                bf[ni][0] = __float_as_uint(Bs[s][k8 + tig    ][col]);
                bf[ni][1] = __float_as_uint(Bs[s][k8 + tig + 4][col]);
            }
#pragma unroll
            for (int mi = 0; mi < 4; mi++)
#pragma unroll
                for (int ni = 0; ni < 4; ni++)
                    mma_tf32(acc[mi][ni], af[mi], bf[ni]);
        }

        if (nxt) {
            CP_WAIT0();
            __syncthreads();
            s ^= 1;
        }
    }

#pragma unroll
    for (int mi = 0; mi < 4; mi++) {
        int r0 = rowBase + warpRow + mi * 16 + gid;
#pragma unroll
        for (int ni = 0; ni < 4; ni++) {
            int c = colBase + warpCol + ni * 8 + tig * 2;
            float2 bz = *(const float2*)&bias[c];
            float2 o0, o1;
            o0.x = acc[mi][ni][0] + bz.x;
            o0.y = acc[mi][ni][1] + bz.y;
            o1.x = acc[mi][ni][2] + bz.x;
            o1.y = acc[mi][ni][3] + bz.y;
            *(float2*)&C[(size_t)r0 * N + c]       = o0;
            *(float2*)&C[(size_t)(r0 + 8) * N + c] = o1;
        }
    }
}

// ---------------------------------------------------------------------------
// Tensor-core causal flash attention.
// QK^T: 3xTF32 (full precision). PV: single tf32 (P in [0,1], error-benign).
// Static smem 44,032 B. 128 threads / 4 warps, BQ=64, key tile 32.
// P aliases K buffer. V and P stored tf32-pre-rounded. Output y stored
// tf32-rounded (numerically identical to out-proj rounding at load).
// ---------------------------------------------------------------------------
#define ABQ 64
#define ABK 32
#define QLD 68
#define KLD 68
#define VLD 72
#define PLD 68

__global__ __launch_bounds__(128)
void attn_tc_kernel(const float* __restrict__ qkv, float* __restrict__ y)
{
    __shared__ float Qs[ABQ * QLD];   // [64][68] fp32
    __shared__ float Us[ABQ * PLD];   // union: Ks [32][68] fp32, then Ps [64][68] tf32
    __shared__ float Vs[ABK * VLD];   // [32][72] tf32-rounded

    const int tid  = threadIdx.x;
    const int warp = tid >> 5;
    const int lane = tid & 31;
    const int gid  = lane >> 2;
    const int tig  = lane & 3;
    const int w16  = warp * 16;
    const int q0   = blockIdx.x * ABQ;
    const int bh   = blockIdx.y;
    const int b    = bh >> 4;
    const int h    = bh & 15;

    const float* base = qkv + (size_t)b * SEQ * QKV_N + h * DHEAD;
    const float* kb   = base + CMODEL;
    const float* vb   = base + 2 * CMODEL;

#pragma unroll
    for (int i = 0; i < 8; i++) {
        int idx = tid + i * 128;
        int r  = idx >> 4;
        int c4 = idx & 15;
        float4 t = *(const float4*)&base[(size_t)(q0 + r) * QKV_N + c4 * 4];
        *(float4*)&Qs[r * QLD + c4 * 4] = t;
    }

    float yacc[8][4];
#pragma unroll
    for (int nt = 0; nt < 8; nt++)
#pragma unroll
        for (int r = 0; r < 4; r++) yacc[nt][r] = 0.f;

    float mprev[2] = {-CUDART_INF_F, -CUDART_INF_F};
    float lrun[2]  = {0.f, 0.f};

    const int nkt   = 2 * blockIdx.x + 2;
    const int rowg0 = q0 + w16 + gid;
    const float SC  = 0.125f;

    for (int kt = 0; kt < nkt; kt++) {
        const int k0 = kt * ABK;
        const bool partial = (kt >= 2 * (int)blockIdx.x);
        __syncthreads();

        // K (fp32, into union) and V (tf32-rounded): 32 rows x 64 cols
#pragma unroll
        for (int i = 0; i < 4; i++) {
            int idx = tid + i * 128;
            int r  = idx >> 4;
            int c4 = idx & 15;
            float4 tk = *(const float4*)&kb[(size_t)(k0 + r) * QKV_N + c4 * 4];
            *(float4*)&Us[r * KLD + c4 * 4] = tk;
            float4 tv = *(const float4*)&vb[(size_t)(k0 + r) * QKV_N + c4 * 4];
            float4 rv;
            rv.x = rtf(tv.x); rv.y = rtf(tv.y);
            rv.z = rtf(tv.z); rv.w = rtf(tv.w);
            *(float4*)&Vs[r * VLD + c4 * 4] = rv;
        }
        __syncthreads();

        // ---- S = Q K^T  (3xTF32) ----
        float sacc[4][4];
#pragma unroll
        for (int ni = 0; ni < 4; ni++)
#pragma unroll
            for (int r = 0; r < 4; r++) sacc[ni][r] = 0.f;

#pragma unroll
        for (int s8 = 0; s8 < 8; s8++) {
            const int kk = s8 * 8;
            float a0 = Qs[(w16 + gid)     * QLD + kk + tig];
            float a1 = Qs[(w16 + gid + 8) * QLD + kk + tig];
            float a2 = Qs[(w16 + gid)     * QLD + kk + tig + 4];
            float a3 = Qs[(w16 + gid + 8) * QLD + kk + tig + 4];
            uint32_t ah[4], al[4];
            split_tf32(a0, ah[0], al[0]);
            split_tf32(a1, ah[1], al[1]);
            split_tf32(a2, ah[2], al[2]);
            split_tf32(a3, ah[3], al[3]);
#pragma unroll
            for (int ni = 0; ni < 4; ni++) {
                float b0 = Us[(ni * 8 + gid) * KLD + kk + tig];
                float b1 = Us[(ni * 8 + gid) * KLD + kk + tig + 4];
                uint32_t bh2[2], bl2[2];
                split_tf32(b0, bh2[0], bl2[0]);
                split_tf32(b1, bh2[1], bl2[1]);
                mma_tf32(sacc[ni], ah, bl2);
                mma_tf32(sacc[ni], al, bh2);
                mma_tf32(sacc[ni], ah, bh2);
            }
        }
        __syncthreads();   // all warps done reading Ks before P overwrites it

        // ---- online softmax ----
        float alpha[2];
#pragma unroll
        for (int hf = 0; hf < 2; hf++) {
            const int rowg = rowg0 + 8 * hf;
            float mt = -CUDART_INF_F;
#pragma unroll
            for (int ni = 0; ni < 4; ni++) {
#pragma unroll
                for (int c = 0; c < 2; c++) {
                    float v = sacc[ni][2 * hf + c] * SC;
                    if (partial) {
                        int key = k0 + ni * 8 + 2 * tig + c;
                        if (key > rowg) v = -CUDART_INF_F;
                    }
                    sacc[ni][2 * hf + c] = v;
                    mt = fmaxf(mt, v);
                }
            }
            mt = fmaxf(mt, __shfl_xor_sync(0xffffffffu, mt, 1));
            mt = fmaxf(mt, __shfl_xor_sync(0xffffffffu, mt, 2));
            float mn = fmaxf(mprev[hf], mt);
            float al2 = __expf(mprev[hf] - mn);
            float lsum = 0.f;
#pragma unroll
            for (int ni = 0; ni < 4; ni++) {
                float p0 = __expf(sacc[ni][2 * hf + 0] - mn);
                float p1 = __expf(sacc[ni][2 * hf + 1] - mn);
                lsum += p0 + p1;
                *(float2*)&Us[(w16 + gid + 8 * hf) * PLD + ni * 8 + 2 * tig] =
                    make_float2(rtf(p0), rtf(p1));
            }
            lsum += __shfl_xor_sync(0xffffffffu, lsum, 1);
            lsum += __shfl_xor_sync(0xffffffffu, lsum, 2);
            lrun[hf] = al2 * lrun[hf] + lsum;
            mprev[hf] = mn;
            alpha[hf] = al2;
        }
#pragma unroll
        for (int nt = 0; nt < 8; nt++) {
            yacc[nt][0] *= alpha[0];
            yacc[nt][1] *= alpha[0];
            yacc[nt][2] *= alpha[1];
            yacc[nt][3] *= alpha[1];
        }
        __syncwarp();   // P stores visible to this warp's fragment loads

        // ---- O += P V  (single tf32; P, V pre-rounded) ----
#pragma unroll
        for (int s8 = 0; s8 < 4; s8++) {
            const int kk = s8 * 8;
            uint32_t ah[4];
            ah[0] = __float_as_uint(Us[(w16 + gid)     * PLD + kk + tig]);
            ah[1] = __float_as_uint(Us[(w16 + gid + 8) * PLD + kk + tig]);
            ah[2] = __float_as_uint(Us[(w16 + gid)     * PLD + kk + tig + 4]);
            ah[3] = __float_as_uint(Us[(w16 + gid + 8) * PLD + kk + tig + 4]);
#pragma unroll
            for (int nt = 0; nt < 8; nt++) {
                uint32_t bv[2];
                bv[0] = __float_as_uint(Vs[(kk + tig)     * VLD + nt * 8 + gid]);
                bv[1] = __float_as_uint(Vs[(kk + tig + 4) * VLD + nt * 8 + gid]);
                mma_tf32(yacc[nt], ah, bv);
            }
        }
    }

    // ---- epilogue: divide by l, round to tf32 (feeds out-proj A), store ----
    float linv0 = 1.f / lrun[0];
    float linv1 = 1.f / lrun[1];
    float* yb = y + (size_t)b * SEQ * CMODEL + h * DHEAD;
#pragma unroll
    for (int nt = 0; nt < 8; nt++) {
        int c = nt * 8 + 2 * tig;
        float2 o0, o1;
        o0.x = rtf(yacc[nt][0] * linv0);
        o0.y = rtf(yacc[nt][1] * linv0);
        o1.x = rtf(yacc[nt][2] * linv1);
        o1.y = rtf(yacc[nt][3] * linv1);
        *(float2*)&yb[(size_t)(rowg0)     * CMODEL + c] = o0;
        *(float2*)&yb[(size_t)(rowg0 + 8) * CMODEL + c] = o1;
    }
}

// ---------------------------------------------------------------------------
// Launch
// ---------------------------------------------------------------------------
extern "C" void kernel_launch(void* const* d_in, const int* in_sizes, int n_in,
                              void* d_out, int out_size)
{
    const float* x     = (const float*)d_in[0];
    const float* w_qkv = (const float*)d_in[1];
    const float* b_qkv = (const float*)d_in[2];
    const float* w_out = (const float*)d_in[3];
    const float* b_out = (const float*)d_in[4];

    float *qkv, *yy, *xc, *wqc, *woc;
    cudaGetSymbolAddress((void**)&qkv, g_qkv);
    cudaGetSymbolAddress((void**)&yy,  g_y);
    cudaGetSymbolAddress((void**)&xc,  g_xc);
    cudaGetSymbolAddress((void**)&wqc, g_wqkvc);
    cudaGetSymbolAddress((void**)&woc, g_woutc);

    float* out = (float*)d_out;

    // 0) pre-round operands to tf32 (numerically identical to cvt-at-load)
    {
        int n4x = MROWS * CMODEL / 4;          // 1,048,576
        cvt_tf32_kernel<<<n4x / 256, 256>>>(x, xc, n4x);
        int n4q = CMODEL * QKV_N / 4;          // 786,432
        cvt_tf32_kernel<<<n4q / 256, 256>>>(w_qkv, wqc, n4q);
        int n4o = CMODEL * CMODEL / 4;         // 262,144
        cvt_tf32_kernel<<<n4o / 256, 256>>>(w_out, woc, n4o);
    }
    // 1) QKV projection
    {
        dim3 grid(QKV_N / BN, MROWS / BM);   // (24, 32)
        tf32_gemm_bias<<<grid, 256>>>(xc, wqc, b_qkv, qkv,
                                      MROWS, QKV_N, CMODEL);
    }
    // 2) causal flash attention
    {
        dim3 grid(SEQ / ABQ, BATCH * NHEADS); // (32, 32)
        attn_tc_kernel<<<grid, 128>>>(qkv, yy);
    }
    // 3) output projection
    {
        dim3 grid(CMODEL / BN, MROWS / BM);  // (8, 32)
        tf32_gemm_bias<<<grid, 256>>>(yy, woc, b_out, out,
                                      MROWS, CMODEL, CMODEL);
    }
}

// round 13
// speedup vs baseline: 2.8163x; 1.0983x over previous
#include <cuda_runtime.h>
#include <cuda_bf16.h>
#include <math_constants.h>
#include <cstdint>

// Problem constants
#define BATCH   2
#define SEQ     2048
#define CMODEL  1024
#define NHEADS  16
#define DHEAD   64
#define MROWS   (BATCH * SEQ)          // 4096
#define QKV_N   (3 * CMODEL)           // 3072

// Scratch (allocation-free rule: __device__ globals)
__device__ float g_qkv[(size_t)MROWS * QKV_N];    // [4096, 3072] Q|K|V (fp32)
__device__ float g_y[(size_t)MROWS * CMODEL];     // [4096, 1024] attn out (tf32-rounded)
__device__ float g_xc[(size_t)MROWS * CMODEL];    // x, tf32-rounded
__device__ float g_wqkvc[(size_t)CMODEL * QKV_N]; // w_qkv, tf32-rounded
__device__ float g_woutc[(size_t)CMODEL * CMODEL];// w_out, tf32-rounded

// ---------------------------------------------------------------------------
// Helpers
// ---------------------------------------------------------------------------
__device__ __forceinline__ uint32_t f2tf32(float x) {
    uint32_t u;
    asm("cvt.rna.tf32.f32 %0, %1;" : "=r"(u) : "f"(x));
    return u;
}
__device__ __forceinline__ float rtf(float x) {
    return __uint_as_float(f2tf32(x));
}

// 3xTF32 split: x ~= hi + lo, each tf32-representable; error ~2^-22
__device__ __forceinline__ void split_tf32(float x, uint32_t& hi, uint32_t& lo) {
    uint32_t h;
    asm("cvt.rna.tf32.f32 %0, %1;" : "=r"(h) : "f"(x));
    float r = x - __uint_as_float(h);
    uint32_t l;
    asm("cvt.rna.tf32.f32 %0, %1;" : "=r"(l) : "f"(r));
    hi = h; lo = l;
}

__device__ __forceinline__ void mma_tf32(float acc[4], const uint32_t a[4],
                                         const uint32_t b[2]) {
    asm("mma.sync.aligned.m16n8k8.row.col.f32.tf32.tf32.f32 "
        "{%0,%1,%2,%3}, {%4,%5,%6,%7}, {%8,%9}, {%0,%1,%2,%3};"
        : "+f"(acc[0]), "+f"(acc[1]), "+f"(acc[2]), "+f"(acc[3])
        : "r"(a[0]), "r"(a[1]), "r"(a[2]), "r"(a[3]), "r"(b[0]), "r"(b[1]));
}

__device__ __forceinline__ void cp16(void* dst, const void* src) {
    uint32_t d = (uint32_t)__cvta_generic_to_shared(dst);
    asm volatile("cp.async.cg.shared.global [%0], [%1], 16;" :: "r"(d), "l"(src));
}
#define CP_COMMIT() asm volatile("cp.async.commit_group;")
#define CP_WAIT0()  asm volatile("cp.async.wait_group 0;")

// ---------------------------------------------------------------------------
// Elementwise tf32 rounding (pre-conversion). n divisible by 4.
// ---------------------------------------------------------------------------
__global__ void cvt_tf32_kernel(const float* __restrict__ in,
                                float* __restrict__ out, int n4)
{
    int i = blockIdx.x * blockDim.x + threadIdx.x;
    if (i < n4) {
        float4 v = ((const float4*)in)[i];
        float4 o;
        o.x = rtf(v.x); o.y = rtf(v.y); o.z = rtf(v.z); o.w = rtf(v.w);
        ((float4*)out)[i] = o;
    }
}

// ---------------------------------------------------------------------------
// TF32 GEMM, fused bias (unchanged from R9 — known good).
// ---------------------------------------------------------------------------
#define BM 128
#define BN 128
#define BKK 16
#define ALD 20
#define LDB 136

__global__ __launch_bounds__(256, 2)
void tf32_gemm_bias(const float* __restrict__ A,
                    const float* __restrict__ B,
                    const float* __restrict__ bias,
                    float* __restrict__ C,
                    int M, int N, int K)
{
    __shared__ float As[2][BM][ALD];
    __shared__ float Bs[2][BKK][LDB];

    const int tid  = threadIdx.x;
    const int warp = tid >> 5;
    const int lane = tid & 31;
    const int gid  = lane >> 2;
    const int tig  = lane & 3;
    const int warpRow = (warp & 1) * 64;
    const int warpCol = (warp >> 1) * 32;
    const int rowBase = blockIdx.y * BM;
    const int colBase = blockIdx.x * BN;

    float acc[4][4][4];
#pragma unroll
    for (int mi = 0; mi < 4; mi++)
#pragma unroll
        for (int ni = 0; ni < 4; ni++)
#pragma unroll
            for (int r = 0; r < 4; r++) acc[mi][ni][r] = 0.f;

#pragma unroll
    for (int i = 0; i < 2; i++) {
        int idx = tid + i * 256;
        int r  = idx >> 2;
        int c4 = idx & 3;
        cp16(&As[0][r][c4 * 4], &A[(size_t)(rowBase + r) * K + c4 * 4]);
    }
#pragma unroll
    for (int i = 0; i < 2; i++) {
        int idx = tid + i * 256;
        int r  = idx >> 5;
        int c4 = idx & 31;
        cp16(&Bs[0][r][c4 * 4], &B[(size_t)r * N + colBase + c4 * 4]);
    }
    CP_COMMIT();
    CP_WAIT0();
    __syncthreads();

    int s = 0;
    for (int k0 = 0; k0 < K; k0 += BKK) {
        const bool nxt = (k0 + BKK) < K;
        if (nxt) {
#pragma unroll
            for (int i = 0; i < 2; i++) {
                int idx = tid + i * 256;
                int r  = idx >> 2;
                int c4 = idx & 3;
                cp16(&As[s ^ 1][r][c4 * 4],
                     &A[(size_t)(rowBase + r) * K + k0 + BKK + c4 * 4]);
            }
#pragma unroll
            for (int i = 0; i < 2; i++) {
                int idx = tid + i * 256;
                int r  = idx >> 5;
                int c4 = idx & 31;
                cp16(&Bs[s ^ 1][r][c4 * 4],
                     &B[(size_t)(k0 + BKK + r) * N + colBase + c4 * 4]);
            }
            CP_COMMIT();
        }

#pragma unroll
        for (int k8 = 0; k8 < BKK; k8 += 8) {
            uint32_t af[4][4], bf[4][2];
#pragma unroll
            for (int mi = 0; mi < 4; mi++) {
                int row = warpRow + mi * 16 + gid;
                af[mi][0] = __float_as_uint(As[s][row    ][k8 + tig]);
                af[mi][1] = __float_as_uint(As[s][row + 8][k8 + tig]);
                af[mi][2] = __float_as_uint(As[s][row    ][k8 + tig + 4]);
                af[mi][3] = __float_as_uint(As[s][row + 8][k8 + tig + 4]);
            }
#pragma unroll
            for (int ni = 0; ni < 4; ni++) {
                int col = warpCol + ni * 8 + gid;
                bf[ni][0] = __float_as_uint(Bs[s][k8 + tig    ][col]);
                bf[ni][1] = __float_as_uint(Bs[s][k8 + tig + 4][col]);
            }
#pragma unroll
            for (int mi = 0; mi < 4; mi++)
#pragma unroll
                for (int ni = 0; ni < 4; ni++)
                    mma_tf32(acc[mi][ni], af[mi], bf[ni]);
        }

        if (nxt) {
            CP_WAIT0();
            __syncthreads();
            s ^= 1;
        }
    }

#pragma unroll
    for (int mi = 0; mi < 4; mi++) {
        int r0 = rowBase + warpRow + mi * 16 + gid;
#pragma unroll
        for (int ni = 0; ni < 4; ni++) {
            int c = colBase + warpCol + ni * 8 + tig * 2;
            float2 bz = *(const float2*)&bias[c];
            float2 o0, o1;
            o0.x = acc[mi][ni][0] + bz.x;
            o0.y = acc[mi][ni][1] + bz.y;
            o1.x = acc[mi][ni][2] + bz.x;
            o1.y = acc[mi][ni][3] + bz.y;
            *(float2*)&C[(size_t)r0 * N + c]       = o0;
            *(float2*)&C[(size_t)(r0 + 8) * N + c] = o1;
        }
    }
}

// ---------------------------------------------------------------------------
// Tensor-core causal flash attention, v4.
// QK^T: 3xTF32. Q hi/lo fragments hoisted to registers (split ONCE before the
// loop); K pre-split into Khi/Klo smem by the loaders (aliased over the dead
// Q staging tile). PV: single tf32 with P routed through a separate smem
// buffer exactly as in the R9-passing kernel (warp-private rows, __syncwarp).
// smem: QKs 17,408 + Ps 17,408 + Vs 9,216 = 44,032 B static.
// ---------------------------------------------------------------------------
#define ABQ 64
#define ABK 32
#define QLD 68
#define KLD 68
#define VLD 72
#define PLD 68

__global__ __launch_bounds__(128)
void attn_tc_kernel(const float* __restrict__ qkv, float* __restrict__ y)
{
    __shared__ float QKs[ABQ * QLD];  // Q staging [64][68]; then Khi[32][68]|Klo[32][68]
    __shared__ float Ps[ABQ * PLD];   // P [64][68], tf32-rounded
    __shared__ float Vs[ABK * VLD];   // V [32][72], tf32-rounded

    float* Khi = QKs;                 // [32][68]
    float* Klo = QKs + 32 * KLD;      // [32][68]

    const int tid  = threadIdx.x;
    const int warp = tid >> 5;
    const int lane = tid & 31;
    const int gid  = lane >> 2;
    const int tig  = lane & 3;
    const int w16  = warp * 16;
    const int q0   = blockIdx.x * ABQ;
    const int bh   = blockIdx.y;
    const int b    = bh >> 4;
    const int h    = bh & 15;

    const float* base = qkv + (size_t)b * SEQ * QKV_N + h * DHEAD;
    const float* kb   = base + CMODEL;
    const float* vb   = base + 2 * CMODEL;

    // Stage Q tile in smem
#pragma unroll
    for (int i = 0; i < 8; i++) {
        int idx = tid + i * 128;
        int r  = idx >> 4;
        int c4 = idx & 15;
        float4 t = *(const float4*)&base[(size_t)(q0 + r) * QKV_N + c4 * 4];
        *(float4*)&QKs[r * QLD + c4 * 4] = t;
    }
    __syncthreads();

    // Build loop-invariant Q hi/lo fragments in registers (split ONCE)
    uint32_t qhi[8][4], qlo[8][4];
#pragma unroll
    for (int s8 = 0; s8 < 8; s8++) {
        const int kk = s8 * 8;
        split_tf32(QKs[(w16 + gid)     * QLD + kk + tig],     qhi[s8][0], qlo[s8][0]);
        split_tf32(QKs[(w16 + gid + 8) * QLD + kk + tig],     qhi[s8][1], qlo[s8][1]);
        split_tf32(QKs[(w16 + gid)     * QLD + kk + tig + 4], qhi[s8][2], qlo[s8][2]);
        split_tf32(QKs[(w16 + gid + 8) * QLD + kk + tig + 4], qhi[s8][3], qlo[s8][3]);
    }
    __syncthreads();   // Q staging reads done before Khi/Klo overwrite the region

    float yacc[8][4];
#pragma unroll
    for (int nt = 0; nt < 8; nt++)
#pragma unroll
        for (int r = 0; r < 4; r++) yacc[nt][r] = 0.f;

    float mprev[2] = {-CUDART_INF_F, -CUDART_INF_F};
    float lrun[2]  = {0.f, 0.f};

    const int nkt   = 2 * blockIdx.x + 2;
    const int rowg0 = q0 + w16 + gid;
    const float SC  = 0.125f;

    for (int kt = 0; kt < nkt; kt++) {
        const int k0 = kt * ABK;
        const bool partial = (kt >= 2 * (int)blockIdx.x);

        // Load K (pre-split hi/lo) and V (tf32-rounded): 32 rows x 64 cols
#pragma unroll
        for (int i = 0; i < 4; i++) {
            int idx = tid + i * 128;
            int r  = idx >> 4;
            int c4 = idx & 15;
            float4 tk = *(const float4*)&kb[(size_t)(k0 + r) * QKV_N + c4 * 4];
            float4 khv, klv;
            uint32_t hh, ll;
            split_tf32(tk.x, hh, ll); khv.x = __uint_as_float(hh); klv.x = __uint_as_float(ll);
            split_tf32(tk.y, hh, ll); khv.y = __uint_as_float(hh); klv.y = __uint_as_float(ll);
            split_tf32(tk.z, hh, ll); khv.z = __uint_as_float(hh); klv.z = __uint_as_float(ll);
            split_tf32(tk.w, hh, ll); khv.w = __uint_as_float(hh); klv.w = __uint_as_float(ll);
            *(float4*)&Khi[r * KLD + c4 * 4] = khv;
            *(float4*)&Klo[r * KLD + c4 * 4] = klv;
            float4 tv = *(const float4*)&vb[(size_t)(k0 + r) * QKV_N + c4 * 4];
            float4 rv;
            rv.x = rtf(tv.x); rv.y = rtf(tv.y);
            rv.z = rtf(tv.z); rv.w = rtf(tv.w);
            *(float4*)&Vs[r * VLD + c4 * 4] = rv;
        }
        __syncthreads();

        // ---- S = Q K^T  (3xTF32; pure LDS+MMA) ----
        float sacc[4][4];
#pragma unroll
        for (int ni = 0; ni < 4; ni++)
#pragma unroll
            for (int r = 0; r < 4; r++) sacc[ni][r] = 0.f;

#pragma unroll
        for (int s8 = 0; s8 < 8; s8++) {
            const int kk = s8 * 8;
#pragma unroll
            for (int ni = 0; ni < 4; ni++) {
                const int rr = (ni * 8 + gid) * KLD + kk + tig;
                uint32_t bh2[2], bl2[2];
                bh2[0] = __float_as_uint(Khi[rr]);
                bh2[1] = __float_as_uint(Khi[rr + 4]);
                bl2[0] = __float_as_uint(Klo[rr]);
                bl2[1] = __float_as_uint(Klo[rr + 4]);
                mma_tf32(sacc[ni], qhi[s8], bl2);
                mma_tf32(sacc[ni], qlo[s8], bh2);
                mma_tf32(sacc[ni], qhi[s8], bh2);
            }
        }

        // ---- online softmax (rows gid and gid+8, replicated in quad) ----
        float alpha[2];
#pragma unroll
        for (int hf = 0; hf < 2; hf++) {
            const int rowg = rowg0 + 8 * hf;
            float mt = -CUDART_INF_F;
#pragma unroll
            for (int ni = 0; ni < 4; ni++) {
#pragma unroll
                for (int c = 0; c < 2; c++) {
                    float v = sacc[ni][2 * hf + c] * SC;
                    if (partial) {
                        int key = k0 + ni * 8 + 2 * tig + c;
                        if (key > rowg) v = -CUDART_INF_F;
                    }
                    sacc[ni][2 * hf + c] = v;
                    mt = fmaxf(mt, v);
                }
            }
            mt = fmaxf(mt, __shfl_xor_sync(0xffffffffu, mt, 1));
            mt = fmaxf(mt, __shfl_xor_sync(0xffffffffu, mt, 2));
            float mn = fmaxf(mprev[hf], mt);
            float al2 = __expf(mprev[hf] - mn);
            float lsum = 0.f;
#pragma unroll
            for (int ni = 0; ni < 4; ni++) {
                float p0 = __expf(sacc[ni][2 * hf + 0] - mn);
                float p1 = __expf(sacc[ni][2 * hf + 1] - mn);
                lsum += p0 + p1;
                *(float2*)&Ps[(w16 + gid + 8 * hf) * PLD + ni * 8 + 2 * tig] =
                    make_float2(rtf(p0), rtf(p1));
            }
            lsum += __shfl_xor_sync(0xffffffffu, lsum, 1);
            lsum += __shfl_xor_sync(0xffffffffu, lsum, 2);
            lrun[hf] = al2 * lrun[hf] + lsum;
            mprev[hf] = mn;
            alpha[hf] = al2;
        }
#pragma unroll
        for (int nt = 0; nt < 8; nt++) {
            yacc[nt][0] *= alpha[0];
            yacc[nt][1] *= alpha[0];
            yacc[nt][2] *= alpha[1];
            yacc[nt][3] *= alpha[1];
        }
        __syncwarp();   // P stores visible to this warp's fragment loads

        // ---- O += P V  (single tf32; P, V pre-rounded; pure LDS+MMA) ----
#pragma unroll
        for (int s8 = 0; s8 < 4; s8++) {
            const int kk = s8 * 8;
            uint32_t af[4];
            af[0] = __float_as_uint(Ps[(w16 + gid)     * PLD + kk + tig]);
            af[1] = __float_as_uint(Ps[(w16 + gid + 8) * PLD + kk + tig]);
            af[2] = __float_as_uint(Ps[(w16 + gid)     * PLD + kk + tig + 4]);
            af[3] = __float_as_uint(Ps[(w16 + gid + 8) * PLD + kk + tig + 4]);
#pragma unroll
            for (int nt = 0; nt < 8; nt++) {
                uint32_t bv[2];
                bv[0] = __float_as_uint(Vs[(kk + tig)     * VLD + nt * 8 + gid]);
                bv[1] = __float_as_uint(Vs[(kk + tig + 4) * VLD + nt * 8 + gid]);
                mma_tf32(yacc[nt], af, bv);
            }
        }
        __syncthreads();   // K/V readers done before next iter's loaders overwrite
    }

    // ---- epilogue: divide by l, round to tf32 (feeds out-proj A), store ----
    float linv0 = 1.f / lrun[0];
    float linv1 = 1.f / lrun[1];
    float* yb = y + (size_t)b * SEQ * CMODEL + h * DHEAD;
#pragma unroll
    for (int nt = 0; nt < 8; nt++) {
        int c = nt * 8 + 2 * tig;
        float2 o0, o1;
        o0.x = rtf(yacc[nt][0] * linv0);
        o0.y = rtf(yacc[nt][1] * linv0);
        o1.x = rtf(yacc[nt][2] * linv1);
        o1.y = rtf(yacc[nt][3] * linv1);
        *(float2*)&yb[(size_t)(rowg0)     * CMODEL + c] = o0;
        *(float2*)&yb[(size_t)(rowg0 + 8) * CMODEL + c] = o1;
    }
}

// ---------------------------------------------------------------------------
// Launch
// ---------------------------------------------------------------------------
extern "C" void kernel_launch(void* const* d_in, const int* in_sizes, int n_in,
                              void* d_out, int out_size)
{
    const float* x     = (const float*)d_in[0];
    const float* w_qkv = (const float*)d_in[1];
    const float* b_qkv = (const float*)d_in[2];
    const float* w_out = (const float*)d_in[3];
    const float* b_out = (const float*)d_in[4];

    float *qkv, *yy, *xc, *wqc, *woc;
    cudaGetSymbolAddress((void**)&qkv, g_qkv);
    cudaGetSymbolAddress((void**)&yy,  g_y);
    cudaGetSymbolAddress((void**)&xc,  g_xc);
    cudaGetSymbolAddress((void**)&wqc, g_wqkvc);
    cudaGetSymbolAddress((void**)&woc, g_woutc);

    float* out = (float*)d_out;

    // 0) pre-round operands to tf32 (numerically identical to cvt-at-load)
    {
        int n4x = MROWS * CMODEL / 4;
        cvt_tf32_kernel<<<n4x / 256, 256>>>(x, xc, n4x);
        int n4q = CMODEL * QKV_N / 4;
        cvt_tf32_kernel<<<n4q / 256, 256>>>(w_qkv, wqc, n4q);
        int n4o = CMODEL * CMODEL / 4;
        cvt_tf32_kernel<<<n4o / 256, 256>>>(w_out, woc, n4o);
    }
    // 1) QKV projection
    {
        dim3 grid(QKV_N / BN, MROWS / BM);   // (24, 32)
        tf32_gemm_bias<<<grid, 256>>>(xc, wqc, b_qkv, qkv,
                                      MROWS, QKV_N, CMODEL);
    }
    // 2) causal flash attention
    {
        dim3 grid(SEQ / ABQ, BATCH * NHEADS); // (32, 32)
        attn_tc_kernel<<<grid, 128>>>(qkv, yy);
    }
    // 3) output projection
    {
        dim3 grid(CMODEL / BN, MROWS / BM);  // (8, 32)
        tf32_gemm_bias<<<grid, 256>>>(yy, woc, b_out, out,
                                      MROWS, CMODEL, CMODEL);
    }
}

// round 15
// speedup vs baseline: 3.1978x; 1.1355x over previous
#include <cuda_runtime.h>
#include <cuda_bf16.h>
#include <math_constants.h>
#include <cstdint>

// Problem constants
#define BATCH   2
#define SEQ     2048
#define CMODEL  1024
#define NHEADS  16
#define DHEAD   64
#define MROWS   (BATCH * SEQ)          // 4096
#define QKV_N   (3 * CMODEL)           // 3072

// Scratch (allocation-free rule: __device__ globals)
__device__ float g_qkv[(size_t)MROWS * QKV_N];    // [4096, 3072] Q|K|V (fp32)
__device__ float g_y[(size_t)MROWS * CMODEL];     // [4096, 1024] attn out (tf32-rounded)
__device__ float g_xc[(size_t)MROWS * CMODEL];    // x, tf32-rounded
__device__ float g_wqkvc[(size_t)CMODEL * QKV_N]; // w_qkv, tf32-rounded
__device__ float g_woutc[(size_t)CMODEL * CMODEL];// w_out, tf32-rounded

// ---------------------------------------------------------------------------
// Helpers
// ---------------------------------------------------------------------------
__device__ __forceinline__ uint32_t f2tf32(float x) {
    uint32_t u;
    asm("cvt.rna.tf32.f32 %0, %1;" : "=r"(u) : "f"(x));
    return u;
}
__device__ __forceinline__ float rtf(float x) {
    return __uint_as_float(f2tf32(x));
}

__device__ __forceinline__ void mma_tf32(float acc[4], const uint32_t a[4],
                                         const uint32_t b[2]) {
    asm("mma.sync.aligned.m16n8k8.row.col.f32.tf32.tf32.f32 "
        "{%0,%1,%2,%3}, {%4,%5,%6,%7}, {%8,%9}, {%0,%1,%2,%3};"
        : "+f"(acc[0]), "+f"(acc[1]), "+f"(acc[2]), "+f"(acc[3])
        : "r"(a[0]), "r"(a[1]), "r"(a[2]), "r"(a[3]), "r"(b[0]), "r"(b[1]));
}

__device__ __forceinline__ void mma_bf16(float acc[4], const uint32_t a[4],
                                         const uint32_t b0, const uint32_t b1) {
    asm("mma.sync.aligned.m16n8k16.row.col.f32.bf16.bf16.f32 "
        "{%0,%1,%2,%3}, {%4,%5,%6,%7}, {%8,%9}, {%0,%1,%2,%3};"
        : "+f"(acc[0]), "+f"(acc[1]), "+f"(acc[2]), "+f"(acc[3])
        : "r"(a[0]), "r"(a[1]), "r"(a[2]), "r"(a[3]), "r"(b0), "r"(b1));
}

// bf16 hi/lo split of two floats -> packed hi pair + packed lo pair.
// Low 16 bits of each pair = element e0 (k-even); high 16 = e1 (k-odd).
// Explicit bit packing: no cvt.bf16x2 operand-order ambiguity.
__device__ __forceinline__ void split_pair_bf16(float e0, float e1,
                                                uint32_t& hi, uint32_t& lo) {
    uint16_t h0 = __bfloat16_as_ushort(__float2bfloat16_rn(e0));
    uint16_t h1 = __bfloat16_as_ushort(__float2bfloat16_rn(e1));
    hi = ((uint32_t)h1 << 16) | h0;
    float r0 = e0 - __uint_as_float((uint32_t)h0 << 16);
    float r1 = e1 - __uint_as_float((uint32_t)h1 << 16);
    uint16_t l0 = __bfloat16_as_ushort(__float2bfloat16_rn(r0));
    uint16_t l1 = __bfloat16_as_ushort(__float2bfloat16_rn(r1));
    lo = ((uint32_t)l1 << 16) | l0;
}

__device__ __forceinline__ void cp16(void* dst, const void* src) {
    uint32_t d = (uint32_t)__cvta_generic_to_shared(dst);
    asm volatile("cp.async.cg.shared.global [%0], [%1], 16;" :: "r"(d), "l"(src));
}
#define CP_COMMIT() asm volatile("cp.async.commit_group;")
#define CP_WAIT0()  asm volatile("cp.async.wait_group 0;")

// ---------------------------------------------------------------------------
// Elementwise tf32 rounding (pre-conversion). n divisible by 4.
// ---------------------------------------------------------------------------
__global__ void cvt_tf32_kernel(const float* __restrict__ in,
                                float* __restrict__ out, int n4)
{
    int i = blockIdx.x * blockDim.x + threadIdx.x;
    if (i < n4) {
        float4 v = ((const float4*)in)[i];
        float4 o;
        o.x = rtf(v.x); o.y = rtf(v.y); o.z = rtf(v.z); o.w = rtf(v.w);
        ((float4*)out)[i] = o;
    }
}

// ---------------------------------------------------------------------------
// TF32 GEMM, fused bias (unchanged from R9/R13 — known good).
// ---------------------------------------------------------------------------
#define BM 128
#define BN 128
#define BKK 16
#define ALD 20
#define LDB 136

__global__ __launch_bounds__(256, 2)
void tf32_gemm_bias(const float* __restrict__ A,
                    const float* __restrict__ B,
                    const float* __restrict__ bias,
                    float* __restrict__ C,
                    int M, int N, int K)
{
    __shared__ float As[2][BM][ALD];
    __shared__ float Bs[2][BKK][LDB];

    const int tid  = threadIdx.x;
    const int warp = tid >> 5;
    const int lane = tid & 31;
    const int gid  = lane >> 2;
    const int tig  = lane & 3;
    const int warpRow = (warp & 1) * 64;
    const int warpCol = (warp >> 1) * 32;
    const int rowBase = blockIdx.y * BM;
    const int colBase = blockIdx.x * BN;

    float acc[4][4][4];
#pragma unroll
    for (int mi = 0; mi < 4; mi++)
#pragma unroll
        for (int ni = 0; ni < 4; ni++)
#pragma unroll
            for (int r = 0; r < 4; r++) acc[mi][ni][r] = 0.f;

#pragma unroll
    for (int i = 0; i < 2; i++) {
        int idx = tid + i * 256;
        int r  = idx >> 2;
        int c4 = idx & 3;
        cp16(&As[0][r][c4 * 4], &A[(size_t)(rowBase + r) * K + c4 * 4]);
    }
#pragma unroll
    for (int i = 0; i < 2; i++) {
        int idx = tid + i * 256;
        int r  = idx >> 5;
        int c4 = idx & 31;
        cp16(&Bs[0][r][c4 * 4], &B[(size_t)r * N + colBase + c4 * 4]);
    }
    CP_COMMIT();
    CP_WAIT0();
    __syncthreads();

    int s = 0;
    for (int k0 = 0; k0 < K; k0 += BKK) {
        const bool nxt = (k0 + BKK) < K;
        if (nxt) {
#pragma unroll
            for (int i = 0; i < 2; i++) {
                int idx = tid + i * 256;
                int r  = idx >> 2;
                int c4 = idx & 3;
                cp16(&As[s ^ 1][r][c4 * 4],
                     &A[(size_t)(rowBase + r) * K + k0 + BKK + c4 * 4]);
            }
#pragma unroll
            for (int i = 0; i < 2; i++) {
                int idx = tid + i * 256;
                int r  = idx >> 5;
                int c4 = idx & 31;
                cp16(&Bs[s ^ 1][r][c4 * 4],
                     &B[(size_t)(k0 + BKK + r) * N + colBase + c4 * 4]);
            }
            CP_COMMIT();
        }

#pragma unroll
        for (int k8 = 0; k8 < BKK; k8 += 8) {
            uint32_t af[4][4], bf[4][2];
#pragma unroll
            for (int mi = 0; mi < 4; mi++) {
                int row = warpRow + mi * 16 + gid;
                af[mi][0] = __float_as_uint(As[s][row    ][k8 + tig]);
                af[mi][1] = __float_as_uint(As[s][row + 8][k8 + tig]);
                af[mi][2] = __float_as_uint(As[s][row    ][k8 + tig + 4]);
                af[mi][3] = __float_as_uint(As[s][row + 8][k8 + tig + 4]);
            }
#pragma unroll
            for (int ni = 0; ni < 4; ni++) {
                int col = warpCol + ni * 8 + gid;
                bf[ni][0] = __float_as_uint(Bs[s][k8 + tig    ][col]);
                bf[ni][1] = __float_as_uint(Bs[s][k8 + tig + 4][col]);
            }
#pragma unroll
            for (int mi = 0; mi < 4; mi++)
#pragma unroll
                for (int ni = 0; ni < 4; ni++)
                    mma_tf32(acc[mi][ni], af[mi], bf[ni]);
        }

        if (nxt) {
            CP_WAIT0();
            __syncthreads();
            s ^= 1;
        }
    }

#pragma unroll
    for (int mi = 0; mi < 4; mi++) {
        int r0 = rowBase + warpRow + mi * 16 + gid;
#pragma unroll
        for (int ni = 0; ni < 4; ni++) {
            int c = colBase + warpCol + ni * 8 + tig * 2;
            float2 bz = *(const float2*)&bias[c];
            float2 o0, o1;
            o0.x = acc[mi][ni][0] + bz.x;
            o0.y = acc[mi][ni][1] + bz.y;
            o1.x = acc[mi][ni][2] + bz.x;
            o1.y = acc[mi][ni][3] + bz.y;
            *(float2*)&C[(size_t)r0 * N + c]       = o0;
            *(float2*)&C[(size_t)(r0 + 8) * N + c] = o1;
        }
    }
}

// ---------------------------------------------------------------------------
// Tensor-core causal flash attention, v5.
// QK^T: 3xBF16 (m16n8k16) — bf16 hi/lo split carries ~16 mantissa bits, dot
// error ~1e-5 over d=64; halves QK mma count AND K-fragment LDS vs 3xTF32.
// Q hi/lo bf16x2 fragments hoisted to registers (32 regs). K pre-split into
// Khi/Klo u32-pair smem (pair-permuted, stride 40 -> conflict-free LDS.64
// b-fragments). PV: single tf32 m16n8k8 via Ps smem, identical to R13.
// smem: Qstage 17,408 (aliased by Khi/Klo 10,240+200pad) + Ps 17,408 +
//       Vs 9,216 = 44,032 B static.
// ---------------------------------------------------------------------------
#define ABQ 64
#define ABK 32
#define QLD 68
#define KPLD 40        // u32 pairs per K row (32 pairs + 8 pad)
#define VLD 72
#define PLD 68

// pair index p (0..31) -> permuted position within row:
// groups of 8: [p0,p4,p1,p5,p2,p6,p3,p7] so (tig, tig+4) pairs sit adjacent.
__device__ __forceinline__ int kpos(int p) {
    return ((p >> 3) << 3) + 2 * (p & 3) + ((p >> 2) & 1);
}

__global__ __launch_bounds__(128)
void attn_tc_kernel(const float* __restrict__ qkv, float* __restrict__ y)
{
    __shared__ float QKs[ABQ * QLD];  // Q staging [64][68]; then Khi|Klo u32 [32][40] each
    __shared__ float Ps[ABQ * PLD];   // P [64][68], tf32-rounded
    __shared__ float Vs[ABK * VLD];   // V [32][72], tf32-rounded

    uint32_t* Khi = (uint32_t*)QKs;           // [32][KPLD]
    uint32_t* Klo = (uint32_t*)QKs + 32 * KPLD;

    const int tid  = threadIdx.x;
    const int warp = tid >> 5;
    const int lane = tid & 31;
    const int gid  = lane >> 2;
    const int tig  = lane & 3;
    const int w16  = warp * 16;
    const int q0   = blockIdx.x * ABQ;
    const int bh   = blockIdx.y;
    const int b    = bh >> 4;
    const int h    = bh & 15;

    const float* base = qkv + (size_t)b * SEQ * QKV_N + h * DHEAD;
    const float* kb   = base + CMODEL;
    const float* vb   = base + 2 * CMODEL;

    // Stage Q tile (fp32) in smem
#pragma unroll
    for (int i = 0; i < 8; i++) {
        int idx = tid + i * 128;
        int r  = idx >> 4;
        int c4 = idx & 15;
        float4 t = *(const float4*)&base[(size_t)(q0 + r) * QKV_N + c4 * 4];
        *(float4*)&QKs[r * QLD + c4 * 4] = t;
    }
    __syncthreads();

    // Build loop-invariant Q bf16 hi/lo A-fragments (m16n8k16), split ONCE.
    // s16 step s covers k = 16s..16s+15. a0=(row,2tig,2tig+1) a1=(row+8,..)
    // a2=(row, 2tig+8, 2tig+9) a3=(row+8, ..).
    uint32_t qhi[4][4], qlo[4][4];
#pragma unroll
    for (int s16 = 0; s16 < 4; s16++) {
        const int kk = s16 * 16;
        const float* r0p = &QKs[(w16 + gid)     * QLD + kk];
        const float* r8p = &QKs[(w16 + gid + 8) * QLD + kk];
        split_pair_bf16(r0p[2 * tig],     r0p[2 * tig + 1], qhi[s16][0], qlo[s16][0]);
        split_pair_bf16(r8p[2 * tig],     r8p[2 * tig + 1], qhi[s16][1], qlo[s16][1]);
        split_pair_bf16(r0p[2 * tig + 8], r0p[2 * tig + 9], qhi[s16][2], qlo[s16][2]);
        split_pair_bf16(r8p[2 * tig + 8], r8p[2 * tig + 9], qhi[s16][3], qlo[s16][3]);
    }
    __syncthreads();   // Q staging reads done before Khi/Klo overwrite the region

    float yacc[8][4];
#pragma unroll
    for (int nt = 0; nt < 8; nt++)
#pragma unroll
        for (int r = 0; r < 4; r++) yacc[nt][r] = 0.f;

    float mprev[2] = {-CUDART_INF_F, -CUDART_INF_F};
    float lrun[2]  = {0.f, 0.f};

    const int nkt   = 2 * blockIdx.x + 2;
    const int rowg0 = q0 + w16 + gid;
    const float SC  = 0.125f;

    for (int kt = 0; kt < nkt; kt++) {
        const int k0 = kt * ABK;
        const bool partial = (kt >= 2 * (int)blockIdx.x);

        // Load K (bf16 hi/lo split, pair-permuted) and V (tf32-rounded)
#pragma unroll
        for (int i = 0; i < 4; i++) {
            int idx = tid + i * 128;
            int r  = idx >> 4;
            int c4 = idx & 15;
            float4 tk = *(const float4*)&kb[(size_t)(k0 + r) * QKV_N + c4 * 4];
            uint32_t h0, l0, h1, l1;
            split_pair_bf16(tk.x, tk.y, h0, l0);   // pair 2*c4
            split_pair_bf16(tk.z, tk.w, h1, l1);   // pair 2*c4+1
            int base0 = r * KPLD + kpos(2 * c4);
            int base1 = r * KPLD + kpos(2 * c4 + 1);
            Khi[base0] = h0;  Khi[base1] = h1;
            Klo[base0] = l0;  Klo[base1] = l1;
            float4 tv = *(const float4*)&vb[(size_t)(k0 + r) * QKV_N + c4 * 4];
            float4 rv;
            rv.x = rtf(tv.x); rv.y = rtf(tv.y);
            rv.z = rtf(tv.z); rv.w = rtf(tv.w);
            *(float4*)&Vs[r * VLD + c4 * 4] = rv;
        }
        __syncthreads();

        // ---- S = Q K^T  (3xBF16 m16n8k16; pure LDS+MMA) ----
        // b0 = pair 8*s16+tig -> pos 8*s16+2tig; b1 = pair +4 -> pos +1 (adjacent)
        float sacc[4][4];
#pragma unroll
        for (int ni = 0; ni < 4; ni++)
#pragma unroll
            for (int r = 0; r < 4; r++) sacc[ni][r] = 0.f;

#pragma unroll
        for (int s16 = 0; s16 < 4; s16++) {
#pragma unroll
            for (int ni = 0; ni < 4; ni++) {
                const int col = ni * 8 + gid;
                const int off = col * KPLD + 8 * s16 + 2 * tig;
                uint2 bhp = *(const uint2*)&Khi[off];
                uint2 blp = *(const uint2*)&Klo[off];
                mma_bf16(sacc[ni], qhi[s16], blp.x, blp.y);
                mma_bf16(sacc[ni], qlo[s16], bhp.x, bhp.y);
                mma_bf16(sacc[ni], qhi[s16], bhp.x, bhp.y);
            }
        }

        // ---- online softmax (rows gid and gid+8, replicated in quad) ----
        float alpha[2];
#pragma unroll
        for (int hf = 0; hf < 2; hf++) {
            const int rowg = rowg0 + 8 * hf;
            float mt = -CUDART_INF_F;
#pragma unroll
            for (int ni = 0; ni < 4; ni++) {
#pragma unroll
                for (int c = 0; c < 2; c++) {
                    float v = sacc[ni][2 * hf + c] * SC;
                    if (partial) {
                        int key = k0 + ni * 8 + 2 * tig + c;
                        if (key > rowg) v = -CUDART_INF_F;
                    }
                    sacc[ni][2 * hf + c] = v;
                    mt = fmaxf(mt, v);
                }
            }
            mt = fmaxf(mt, __shfl_xor_sync(0xffffffffu, mt, 1));
            mt = fmaxf(mt, __shfl_xor_sync(0xffffffffu, mt, 2));
            float mn = fmaxf(mprev[hf], mt);
            float al2 = __expf(mprev[hf] - mn);
            float lsum = 0.f;
#pragma unroll
            for (int ni = 0; ni < 4; ni++) {
                float p0 = __expf(sacc[ni][2 * hf + 0] - mn);
                float p1 = __expf(sacc[ni][2 * hf + 1] - mn);
                lsum += p0 + p1;
                *(float2*)&Ps[(w16 + gid + 8 * hf) * PLD + ni * 8 + 2 * tig] =
                    make_float2(rtf(p0), rtf(p1));
            }
            lsum += __shfl_xor_sync(0xffffffffu, lsum, 1);
            lsum += __shfl_xor_sync(0xffffffffu, lsum, 2);
            lrun[hf] = al2 * lrun[hf] + lsum;
            mprev[hf] = mn;
            alpha[hf] = al2;
        }
#pragma unroll
        for (int nt = 0; nt < 8; nt++) {
            yacc[nt][0] *= alpha[0];
            yacc[nt][1] *= alpha[0];
            yacc[nt][2] *= alpha[1];
            yacc[nt][3] *= alpha[1];
        }
        __syncwarp();   // P stores visible to this warp's fragment loads

        // ---- O += P V  (single tf32 m16n8k8; P, V pre-rounded) ----
#pragma unroll
        for (int s8 = 0; s8 < 4; s8++) {
            const int kk = s8 * 8;
            uint32_t af[4];
            af[0] = __float_as_uint(Ps[(w16 + gid)     * PLD + kk + tig]);
            af[1] = __float_as_uint(Ps[(w16 + gid + 8) * PLD + kk + tig]);
            af[2] = __float_as_uint(Ps[(w16 + gid)     * PLD + kk + tig + 4]);
            af[3] = __float_as_uint(Ps[(w16 + gid + 8) * PLD + kk + tig + 4]);
#pragma unroll
            for (int nt = 0; nt < 8; nt++) {
                uint32_t bv[2];
                bv[0] = __float_as_uint(Vs[(kk + tig)     * VLD + nt * 8 + gid]);
                bv[1] = __float_as_uint(Vs[(kk + tig + 4) * VLD + nt * 8 + gid]);
                mma_tf32(yacc[nt], af, bv);
            }
        }
        __syncthreads();   // K/V/P readers done before next iter's loaders overwrite
    }

    // ---- epilogue: divide by l, round to tf32 (feeds out-proj A), store ----
    float linv0 = 1.f / lrun[0];
    float linv1 = 1.f / lrun[1];
    float* yb = y + (size_t)b * SEQ * CMODEL + h * DHEAD;
#pragma unroll
    for (int nt = 0; nt < 8; nt++) {
        int c = nt * 8 + 2 * tig;
        float2 o0, o1;
        o0.x = rtf(yacc[nt][0] * linv0);
        o0.y = rtf(yacc[nt][1] * linv0);
        o1.x = rtf(yacc[nt][2] * linv1);
        o1.y = rtf(yacc[nt][3] * linv1);
        *(float2*)&yb[(size_t)(rowg0)     * CMODEL + c] = o0;
        *(float2*)&yb[(size_t)(rowg0 + 8) * CMODEL + c] = o1;
    }
}

// ---------------------------------------------------------------------------
// Launch
// ---------------------------------------------------------------------------
extern "C" void kernel_launch(void* const* d_in, const int* in_sizes, int n_in,
                              void* d_out, int out_size)
{
    const float* x     = (const float*)d_in[0];
    const float* w_qkv = (const float*)d_in[1];
    const float* b_qkv = (const float*)d_in[2];
    const float* w_out = (const float*)d_in[3];
    const float* b_out = (const float*)d_in[4];

    float *qkv, *yy, *xc, *wqc, *woc;
    cudaGetSymbolAddress((void**)&qkv, g_qkv);
    cudaGetSymbolAddress((void**)&yy,  g_y);
    cudaGetSymbolAddress((void**)&xc,  g_xc);
    cudaGetSymbolAddress((void**)&wqc, g_wqkvc);
    cudaGetSymbolAddress((void**)&woc, g_woutc);

    float* out = (float*)d_out;

    // 0) pre-round operands to tf32 (numerically identical to cvt-at-load)
    {
        int n4x = MROWS * CMODEL / 4;
        cvt_tf32_kernel<<<n4x / 256, 256>>>(x, xc, n4x);
        int n4q = CMODEL * QKV_N / 4;
        cvt_tf32_kernel<<<n4q / 256, 256>>>(w_qkv, wqc, n4q);
        int n4o = CMODEL * CMODEL / 4;
        cvt_tf32_kernel<<<n4o / 256, 256>>>(w_out, woc, n4o);
    }
    // 1) QKV projection
    {
        dim3 grid(QKV_N / BN, MROWS / BM);   // (24, 32)
        tf32_gemm_bias<<<grid, 256>>>(xc, wqc, b_qkv, qkv,
                                      MROWS, QKV_N, CMODEL);
    }
    // 2) causal flash attention
    {
        dim3 grid(SEQ / ABQ, BATCH * NHEADS); // (32, 32)
        attn_tc_kernel<<<grid, 128>>>(qkv, yy);
    }
    // 3) output projection
    {
        dim3 grid(CMODEL / BN, MROWS / BM);  // (8, 32)
        tf32_gemm_bias<<<grid, 256>>>(yy, woc, b_out, out,
                                      MROWS, CMODEL, CMODEL);
    }
}

// round 16
// speedup vs baseline: 3.2958x; 1.0306x over previous
#include <cuda_runtime.h>
#include <cuda_bf16.h>
#include <math_constants.h>
#include <cstdint>

// Problem constants
#define BATCH   2
#define SEQ     2048
#define CMODEL  1024
#define NHEADS  16
#define DHEAD   64
#define MROWS   (BATCH * SEQ)          // 4096
#define QKV_N   (3 * CMODEL)           // 3072

// Scratch (allocation-free rule: __device__ globals)
__device__ float g_qkv[(size_t)MROWS * QKV_N];    // [4096, 3072] Q|K|V (fp32)
__device__ float g_y[(size_t)MROWS * CMODEL];     // [4096, 1024] attn out (tf32-rounded)
__device__ float g_xc[(size_t)MROWS * CMODEL];    // x, tf32-rounded
__device__ float g_wqkvc[(size_t)CMODEL * QKV_N]; // w_qkv, tf32-rounded
__device__ float g_woutc[(size_t)CMODEL * CMODEL];// w_out, tf32-rounded

// ---------------------------------------------------------------------------
// Helpers
// ---------------------------------------------------------------------------
__device__ __forceinline__ uint32_t f2tf32(float x) {
    uint32_t u;
    asm("cvt.rna.tf32.f32 %0, %1;" : "=r"(u) : "f"(x));
    return u;
}
__device__ __forceinline__ float rtf(float x) {
    return __uint_as_float(f2tf32(x));
}

__device__ __forceinline__ void mma_tf32(float acc[4], const uint32_t a[4],
                                         const uint32_t b[2]) {
    asm("mma.sync.aligned.m16n8k8.row.col.f32.tf32.tf32.f32 "
        "{%0,%1,%2,%3}, {%4,%5,%6,%7}, {%8,%9}, {%0,%1,%2,%3};"
        : "+f"(acc[0]), "+f"(acc[1]), "+f"(acc[2]), "+f"(acc[3])
        : "r"(a[0]), "r"(a[1]), "r"(a[2]), "r"(a[3]), "r"(b[0]), "r"(b[1]));
}

__device__ __forceinline__ void mma_bf16(float acc[4], const uint32_t a[4],
                                         const uint32_t b0, const uint32_t b1) {
    asm("mma.sync.aligned.m16n8k16.row.col.f32.bf16.bf16.f32 "
        "{%0,%1,%2,%3}, {%4,%5,%6,%7}, {%8,%9}, {%0,%1,%2,%3};"
        : "+f"(acc[0]), "+f"(acc[1]), "+f"(acc[2]), "+f"(acc[3])
        : "r"(a[0]), "r"(a[1]), "r"(a[2]), "r"(a[3]), "r"(b0), "r"(b1));
}

// bf16 hi/lo split of two floats -> packed hi pair + packed lo pair.
__device__ __forceinline__ void split_pair_bf16(float e0, float e1,
                                                uint32_t& hi, uint32_t& lo) {
    uint16_t h0 = __bfloat16_as_ushort(__float2bfloat16_rn(e0));
    uint16_t h1 = __bfloat16_as_ushort(__float2bfloat16_rn(e1));
    hi = ((uint32_t)h1 << 16) | h0;
    float r0 = e0 - __uint_as_float((uint32_t)h0 << 16);
    float r1 = e1 - __uint_as_float((uint32_t)h1 << 16);
    uint16_t l0 = __bfloat16_as_ushort(__float2bfloat16_rn(r0));
    uint16_t l1 = __bfloat16_as_ushort(__float2bfloat16_rn(r1));
    lo = ((uint32_t)l1 << 16) | l0;
}

__device__ __forceinline__ void cp16(void* dst, const void* src) {
    uint32_t d = (uint32_t)__cvta_generic_to_shared(dst);
    asm volatile("cp.async.cg.shared.global [%0], [%1], 16;" :: "r"(d), "l"(src));
}
#define CP_COMMIT() asm volatile("cp.async.commit_group;")
#define CP_WAIT0()  asm volatile("cp.async.wait_group 0;")

// ---------------------------------------------------------------------------
// Elementwise tf32 rounding (pre-conversion). n divisible by 4.
// ---------------------------------------------------------------------------
__global__ void cvt_tf32_kernel(const float* __restrict__ in,
                                float* __restrict__ out, int n4)
{
    int i = blockIdx.x * blockDim.x + threadIdx.x;
    if (i < n4) {
        float4 v = ((const float4*)in)[i];
        float4 o;
        o.x = rtf(v.x); o.y = rtf(v.y); o.z = rtf(v.z); o.w = rtf(v.w);
        ((float4*)out)[i] = o;
    }
}

// ---------------------------------------------------------------------------
// TF32 GEMM, fused bias (unchanged from R9/R13/R15 — known good).
// ---------------------------------------------------------------------------
#define BM 128
#define BN 128
#define BKK 16
#define ALD 20
#define LDB 136

__global__ __launch_bounds__(256, 2)
void tf32_gemm_bias(const float* __restrict__ A,
                    const float* __restrict__ B,
                    const float* __restrict__ bias,
                    float* __restrict__ C,
                    int M, int N, int K)
{
    __shared__ float As[2][BM][ALD];
    __shared__ float Bs[2][BKK][LDB];

    const int tid  = threadIdx.x;
    const int warp = tid >> 5;
    const int lane = tid & 31;
    const int gid  = lane >> 2;
    const int tig  = lane & 3;
    const int warpRow = (warp & 1) * 64;
    const int warpCol = (warp >> 1) * 32;
    const int rowBase = blockIdx.y * BM;
    const int colBase = blockIdx.x * BN;

    float acc[4][4][4];
#pragma unroll
    for (int mi = 0; mi < 4; mi++)
#pragma unroll
        for (int ni = 0; ni < 4; ni++)
#pragma unroll
            for (int r = 0; r < 4; r++) acc[mi][ni][r] = 0.f;

#pragma unroll
    for (int i = 0; i < 2; i++) {
        int idx = tid + i * 256;
        int r  = idx >> 2;
        int c4 = idx & 3;
        cp16(&As[0][r][c4 * 4], &A[(size_t)(rowBase + r) * K + c4 * 4]);
    }
#pragma unroll
    for (int i = 0; i < 2; i++) {
        int idx = tid + i * 256;
        int r  = idx >> 5;
        int c4 = idx & 31;
        cp16(&Bs[0][r][c4 * 4], &B[(size_t)r * N + colBase + c4 * 4]);
    }
    CP_COMMIT();
    CP_WAIT0();
    __syncthreads();

    int s = 0;
    for (int k0 = 0; k0 < K; k0 += BKK) {
        const bool nxt = (k0 + BKK) < K;
        if (nxt) {
#pragma unroll
            for (int i = 0; i < 2; i++) {
                int idx = tid + i * 256;
                int r  = idx >> 2;
                int c4 = idx & 3;
                cp16(&As[s ^ 1][r][c4 * 4],
                     &A[(size_t)(rowBase + r) * K + k0 + BKK + c4 * 4]);
            }
#pragma unroll
            for (int i = 0; i < 2; i++) {
                int idx = tid + i * 256;
                int r  = idx >> 5;
                int c4 = idx & 31;
                cp16(&Bs[s ^ 1][r][c4 * 4],
                     &B[(size_t)(k0 + BKK + r) * N + colBase + c4 * 4]);
            }
            CP_COMMIT();
        }

#pragma unroll
        for (int k8 = 0; k8 < BKK; k8 += 8) {
            uint32_t af[4][4], bf[4][2];
#pragma unroll
            for (int mi = 0; mi < 4; mi++) {
                int row = warpRow + mi * 16 + gid;
                af[mi][0] = __float_as_uint(As[s][row    ][k8 + tig]);
                af[mi][1] = __float_as_uint(As[s][row + 8][k8 + tig]);
                af[mi][2] = __float_as_uint(As[s][row    ][k8 + tig + 4]);
                af[mi][3] = __float_as_uint(As[s][row + 8][k8 + tig + 4]);
            }
#pragma unroll
            for (int ni = 0; ni < 4; ni++) {
                int col = warpCol + ni * 8 + gid;
                bf[ni][0] = __float_as_uint(Bs[s][k8 + tig    ][col]);
                bf[ni][1] = __float_as_uint(Bs[s][k8 + tig + 4][col]);
            }
#pragma unroll
            for (int mi = 0; mi < 4; mi++)
#pragma unroll
                for (int ni = 0; ni < 4; ni++)
                    mma_tf32(acc[mi][ni], af[mi], bf[ni]);
        }

        if (nxt) {
            CP_WAIT0();
            __syncthreads();
            s ^= 1;
        }
    }

#pragma unroll
    for (int mi = 0; mi < 4; mi++) {
        int r0 = rowBase + warpRow + mi * 16 + gid;
#pragma unroll
        for (int ni = 0; ni < 4; ni++) {
            int c = colBase + warpCol + ni * 8 + tig * 2;
            float2 bz = *(const float2*)&bias[c];
            float2 o0, o1;
            o0.x = acc[mi][ni][0] + bz.x;
            o0.y = acc[mi][ni][1] + bz.y;
            o1.x = acc[mi][ni][2] + bz.x;
            o1.y = acc[mi][ni][3] + bz.y;
            *(float2*)&C[(size_t)r0 * N + c]       = o0;
            *(float2*)&C[(size_t)(r0 + 8) * N + c] = o1;
        }
    }
}

// ---------------------------------------------------------------------------
// Tensor-core causal flash attention, v6.
// vs v5: (1) key tile 32->64 — halves per-key softmax bookkeeping, yacc
// rescale and sync overhead; (2) balanced q-tile pairing — grid.x=16, each
// CTA runs q-tile bx then 31-bx => constant 33 key-tiles per CTA, one
// uniform resident wave (no ragged tail).
// smem (38,912 B static, two regions):
//  region A (20,480 B): Q staging [64][68] -> Khi|Klo u32 [64][40] each
//                       -> Ps [64][68] (aliases dead K after S phase)
//  region B (18,432 B): Vs [64][72] tf32-rounded
// QK^T: 3xBF16 m16n8k16 (Q frags hoisted per tile). PV: single tf32 m16n8k8.
// ---------------------------------------------------------------------------
#define ABQ 64
#define ABK 64
#define QLD 68
#define KPLD 40        // u32 pairs per K row (32 pairs + 8 pad)
#define VLD 72
#define PLD 68
#define REGA_BYTES (2 * ABK * KPLD * 4)          // 20,480
#define REGB_BYTES (ABK * VLD * 4)               // 18,432

// pair index p (0..31) -> permuted position within row:
// groups of 8: [p0,p4,p1,p5,p2,p6,p3,p7] so (tig, tig+4) pairs sit adjacent.
__device__ __forceinline__ int kpos(int p) {
    return ((p >> 3) << 3) + 2 * (p & 3) + ((p >> 2) & 1);
}

__global__ __launch_bounds__(128)
void attn_tc_kernel(const float* __restrict__ qkv, float* __restrict__ y)
{
    __shared__ __align__(16) unsigned char smraw[REGA_BYTES + REGB_BYTES];
    float*    QKs = (float*)smraw;                 // Q staging [64][68]
    uint32_t* Khi = (uint32_t*)smraw;              // [64][40]
    uint32_t* Klo = Khi + ABK * KPLD;              // [64][40]
    float*    Ps  = (float*)smraw;                 // [64][68] (aliases K region)
    float*    Vs  = (float*)(smraw + REGA_BYTES);  // [64][72]

    const int tid  = threadIdx.x;
    const int warp = tid >> 5;
    const int lane = tid & 31;
    const int gid  = lane >> 2;
    const int tig  = lane & 3;
    const int w16  = warp * 16;
    const int bh   = blockIdx.y;
    const int b    = bh >> 4;
    const int h    = bh & 15;

    const float* base = qkv + (size_t)b * SEQ * QKV_N + h * DHEAD;
    const float* kb   = base + CMODEL;
    const float* vb   = base + 2 * CMODEL;
    float* yb = y + (size_t)b * SEQ * CMODEL + h * DHEAD;
    const float SC = 0.125f;

#pragma unroll 1
    for (int ti = 0; ti < 2; ti++) {
        const int qt = (ti == 0) ? (int)blockIdx.x : 31 - (int)blockIdx.x;
        const int q0 = qt * ABQ;
        const int rowg0 = q0 + w16 + gid;

        // ---- stage Q tile (fp32) into region A ----
#pragma unroll
        for (int i = 0; i < 8; i++) {
            int idx = tid + i * 128;
            int r  = idx >> 4;
            int c4 = idx & 15;
            float4 t = *(const float4*)&base[(size_t)(q0 + r) * QKV_N + c4 * 4];
            *(float4*)&QKs[r * QLD + c4 * 4] = t;
        }
        __syncthreads();

        // ---- build loop-invariant Q bf16 hi/lo A-fragments (split ONCE) ----
        uint32_t qhi[4][4], qlo[4][4];
#pragma unroll
        for (int s16 = 0; s16 < 4; s16++) {
            const int kk = s16 * 16;
            const float* r0p = &QKs[(w16 + gid)     * QLD + kk];
            const float* r8p = &QKs[(w16 + gid + 8) * QLD + kk];
            split_pair_bf16(r0p[2 * tig],     r0p[2 * tig + 1], qhi[s16][0], qlo[s16][0]);
            split_pair_bf16(r8p[2 * tig],     r8p[2 * tig + 1], qhi[s16][1], qlo[s16][1]);
            split_pair_bf16(r0p[2 * tig + 8], r0p[2 * tig + 9], qhi[s16][2], qlo[s16][2]);
            split_pair_bf16(r8p[2 * tig + 8], r8p[2 * tig + 9], qhi[s16][3], qlo[s16][3]);
        }
        __syncthreads();   // Q staging reads done before K loader overwrites

        float yacc[8][4];
#pragma unroll
        for (int nt = 0; nt < 8; nt++)
#pragma unroll
            for (int r = 0; r < 4; r++) yacc[nt][r] = 0.f;

        float mprev[2] = {-CUDART_INF_F, -CUDART_INF_F};
        float lrun[2]  = {0.f, 0.f};

        const int nkt = qt + 1;
#pragma unroll 1
        for (int kt = 0; kt < nkt; kt++) {
            const int k0 = kt * ABK;
            const bool partial = (kt == qt);

            // ---- load K (bf16 hi/lo, pair-permuted) + V (tf32-rounded) ----
#pragma unroll
            for (int i = 0; i < 8; i++) {
                int idx = tid + i * 128;
                int r  = idx >> 4;        // 0..63
                int c4 = idx & 15;
                float4 tk = *(const float4*)&kb[(size_t)(k0 + r) * QKV_N + c4 * 4];
                uint32_t h0, l0, h1, l1;
                split_pair_bf16(tk.x, tk.y, h0, l0);
                split_pair_bf16(tk.z, tk.w, h1, l1);
                int p0 = r * KPLD + kpos(2 * c4);
                int p1 = r * KPLD + kpos(2 * c4 + 1);
                Khi[p0] = h0;  Khi[p1] = h1;
                Klo[p0] = l0;  Klo[p1] = l1;
                float4 tv = *(const float4*)&vb[(size_t)(k0 + r) * QKV_N + c4 * 4];
                float4 rv;
                rv.x = rtf(tv.x); rv.y = rtf(tv.y);
                rv.z = rtf(tv.z); rv.w = rtf(tv.w);
                *(float4*)&Vs[r * VLD + c4 * 4] = rv;
            }
            __syncthreads();

            // ---- S = Q K^T  (3xBF16 m16n8k16) ----
            float sacc[8][4];
#pragma unroll
            for (int ni = 0; ni < 8; ni++)
#pragma unroll
                for (int r = 0; r < 4; r++) sacc[ni][r] = 0.f;

#pragma unroll
            for (int s16 = 0; s16 < 4; s16++) {
#pragma unroll
                for (int ni = 0; ni < 8; ni++) {
                    const int col = ni * 8 + gid;
                    const int off = col * KPLD + 8 * s16 + 2 * tig;
                    uint2 bhp = *(const uint2*)&Khi[off];
                    uint2 blp = *(const uint2*)&Klo[off];
                    mma_bf16(sacc[ni], qhi[s16], blp.x, blp.y);
                    mma_bf16(sacc[ni], qlo[s16], bhp.x, bhp.y);
                    mma_bf16(sacc[ni], qhi[s16], bhp.x, bhp.y);
                }
            }
            __syncthreads();   // K fully dead before Ps overwrites region A

            // ---- online softmax; write P (tf32-rounded) to Ps ----
            float alpha[2];
#pragma unroll
            for (int hf = 0; hf < 2; hf++) {
                const int rowg = rowg0 + 8 * hf;
                float mt = -CUDART_INF_F;
#pragma unroll
                for (int ni = 0; ni < 8; ni++) {
#pragma unroll
                    for (int c = 0; c < 2; c++) {
                        float v = sacc[ni][2 * hf + c] * SC;
                        if (partial) {
                            int key = k0 + ni * 8 + 2 * tig + c;
                            if (key > rowg) v = -CUDART_INF_F;
                        }
                        sacc[ni][2 * hf + c] = v;
                        mt = fmaxf(mt, v);
                    }
                }
                mt = fmaxf(mt, __shfl_xor_sync(0xffffffffu, mt, 1));
                mt = fmaxf(mt, __shfl_xor_sync(0xffffffffu, mt, 2));
                float mn = fmaxf(mprev[hf], mt);
                float al2 = __expf(mprev[hf] - mn);
                float lsum = 0.f;
#pragma unroll
                for (int ni = 0; ni < 8; ni++) {
                    float p0 = __expf(sacc[ni][2 * hf + 0] - mn);
                    float p1 = __expf(sacc[ni][2 * hf + 1] - mn);
                    lsum += p0 + p1;
                    *(float2*)&Ps[(w16 + gid + 8 * hf) * PLD + ni * 8 + 2 * tig] =
                        make_float2(rtf(p0), rtf(p1));
                }
                lsum += __shfl_xor_sync(0xffffffffu, lsum, 1);
                lsum += __shfl_xor_sync(0xffffffffu, lsum, 2);
                lrun[hf] = al2 * lrun[hf] + lsum;
                mprev[hf] = mn;
                alpha[hf] = al2;
            }
#pragma unroll
            for (int nt = 0; nt < 8; nt++) {
                yacc[nt][0] *= alpha[0];
                yacc[nt][1] *= alpha[0];
                yacc[nt][2] *= alpha[1];
                yacc[nt][3] *= alpha[1];
            }
            __syncwarp();   // own-warp P rows visible to own fragment loads

            // ---- O += P V  (single tf32 m16n8k8; 64-deep K) ----
#pragma unroll
            for (int s8 = 0; s8 < 8; s8++) {
                const int kk = s8 * 8;
                uint32_t af[4];
                af[0] = __float_as_uint(Ps[(w16 + gid)     * PLD + kk + tig]);
                af[1] = __float_as_uint(Ps[(w16 + gid + 8) * PLD + kk + tig]);
                af[2] = __float_as_uint(Ps[(w16 + gid)     * PLD + kk + tig + 4]);
                af[3] = __float_as_uint(Ps[(w16 + gid + 8) * PLD + kk + tig + 4]);
#pragma unroll
                for (int nt = 0; nt < 8; nt++) {
                    uint32_t bv[2];
                    bv[0] = __float_as_uint(Vs[(kk + tig)     * VLD + nt * 8 + gid]);
                    bv[1] = __float_as_uint(Vs[(kk + tig + 4) * VLD + nt * 8 + gid]);
                    mma_tf32(yacc[nt], af, bv);
                }
            }
            __syncthreads();   // P/V readers done before next loaders overwrite
        }

        // ---- epilogue for this tile: divide by l, round to tf32, store ----
        float linv0 = 1.f / lrun[0];
        float linv1 = 1.f / lrun[1];
#pragma unroll
        for (int nt = 0; nt < 8; nt++) {
            int c = nt * 8 + 2 * tig;
            float2 o0, o1;
            o0.x = rtf(yacc[nt][0] * linv0);
            o0.y = rtf(yacc[nt][1] * linv0);
            o1.x = rtf(yacc[nt][2] * linv1);
            o1.y = rtf(yacc[nt][3] * linv1);
            *(float2*)&yb[(size_t)(rowg0)     * CMODEL + c] = o0;
            *(float2*)&yb[(size_t)(rowg0 + 8) * CMODEL + c] = o1;
        }
    }
}

// ---------------------------------------------------------------------------
// Launch
// ---------------------------------------------------------------------------
extern "C" void kernel_launch(void* const* d_in, const int* in_sizes, int n_in,
                              void* d_out, int out_size)
{
    const float* x     = (const float*)d_in[0];
    const float* w_qkv = (const float*)d_in[1];
    const float* b_qkv = (const float*)d_in[2];
    const float* w_out = (const float*)d_in[3];
    const float* b_out = (const float*)d_in[4];

    float *qkv, *yy, *xc, *wqc, *woc;
    cudaGetSymbolAddress((void**)&qkv, g_qkv);
    cudaGetSymbolAddress((void**)&yy,  g_y);
    cudaGetSymbolAddress((void**)&xc,  g_xc);
    cudaGetSymbolAddress((void**)&wqc, g_wqkvc);
    cudaGetSymbolAddress((void**)&woc, g_woutc);

    float* out = (float*)d_out;

    // 0) pre-round operands to tf32 (numerically identical to cvt-at-load)
    {
        int n4x = MROWS * CMODEL / 4;
        cvt_tf32_kernel<<<n4x / 256, 256>>>(x, xc, n4x);
        int n4q = CMODEL * QKV_N / 4;
        cvt_tf32_kernel<<<n4q / 256, 256>>>(w_qkv, wqc, n4q);
        int n4o = CMODEL * CMODEL / 4;
        cvt_tf32_kernel<<<n4o / 256, 256>>>(w_out, woc, n4o);
    }
    // 1) QKV projection
    {
        dim3 grid(QKV_N / BN, MROWS / BM);   // (24, 32)
        tf32_gemm_bias<<<grid, 256>>>(xc, wqc, b_qkv, qkv,
                                      MROWS, QKV_N, CMODEL);
    }
    // 2) causal flash attention (paired q-tiles: bx and 31-bx)
    {
        dim3 grid(16, BATCH * NHEADS);       // (16, 32), 512 uniform CTAs
        attn_tc_kernel<<<grid, 128>>>(qkv, yy);
    }
    // 3) output projection
    {
        dim3 grid(CMODEL / BN, MROWS / BM);  // (8, 32)
        tf32_gemm_bias<<<grid, 256>>>(yy, woc, b_out, out,
                                      MROWS, CMODEL, CMODEL);
    }
}